// round 10
// baseline (speedup 1.0000x reference)
#include <cuda_runtime.h>
#include <cuda_bf16.h>
#include <math.h>
#include <stdint.h>

#define BB 4
#define SS 2048
#define HD 1024
#define NH 8
#define DK 128
#define WA 67
#define BH (BB*NH)
#define NROWS (BH*SS)
#define OUT1_ELEMS (BB*SS*NH*WA)
#define OW (NH*WA)
#define SCALE 0.08838834764831845f

// ---------------- scratch (device globals; no allocation allowed) ----------------
__device__ float g_V[BB*SS*HD];
__device__ __nv_bfloat16 g_cDh[BH*80*SS];     // transposed: [bh][w(80, zero-padded)][s]
__device__ __nv_bfloat16 g_cDl[BH*80*SS];
__device__ __nv_bfloat16 g_Xhi[BB*SS*HD];
__device__ __nv_bfloat16 g_Xlo[BB*SS*HD];
__device__ __nv_bfloat16 g_Whi[3*HD*HD];
__device__ __nv_bfloat16 g_Wlo[3*HD*HD];
__device__ __nv_bfloat16 g_Qhi[BB*SS*HD];
__device__ __nv_bfloat16 g_Qlo[BB*SS*HD];
__device__ __nv_bfloat16 g_Khi[BB*SS*HD];
__device__ __nv_bfloat16 g_Klo[BB*SS*HD];

// db4 filters, pre-reversed:  g[t] = DEC[7-t]
__constant__ float REV_LO[8] = {
    0.23037781330885523f,  0.7148465705525415f,   0.6308807679295904f,
   -0.02798376941698385f, -0.18703481171888114f,  0.030841381835986965f,
    0.032883011666982945f,-0.010597401784997278f };
__constant__ float REV_HI[8] = {
   -0.010597401784997278f,-0.032883011666982945f, 0.030841381835986965f,
    0.18703481171888114f, -0.02798376941698385f, -0.6308807679295904f,
    0.7148465705525415f,  -0.23037781330885523f };

// ---------------- helpers ----------------
__device__ __forceinline__ uint32_t smem_u32(const void* p) {
    uint32_t a;
    asm("{ .reg .u64 t; cvta.to.shared.u64 t, %1; cvt.u32.u64 %0, t; }" : "=r"(a) : "l"(p));
    return a;
}
__device__ __forceinline__ void cp16(uint32_t s, const void* g) {
    asm volatile("cp.async.cg.shared.global [%0], [%1], 16;" :: "r"(s), "l"(g));
}
__device__ __forceinline__ void mma16816(float* d,
    uint32_t a0, uint32_t a1, uint32_t a2, uint32_t a3, uint32_t b0, uint32_t b1) {
    asm volatile(
        "mma.sync.aligned.m16n8k16.row.col.f32.bf16.bf16.f32 "
        "{%0,%1,%2,%3}, {%4,%5,%6,%7}, {%8,%9}, {%0,%1,%2,%3};"
        : "+f"(d[0]), "+f"(d[1]), "+f"(d[2]), "+f"(d[3])
        : "r"(a0), "r"(a1), "r"(a2), "r"(a3), "r"(b0), "r"(b1));
}
__device__ __forceinline__ void ldm_x4(uint32_t* r, uint32_t addr) {
    asm volatile("ldmatrix.sync.aligned.m8n8.x4.shared.b16 {%0,%1,%2,%3}, [%4];"
        : "=r"(r[0]), "=r"(r[1]), "=r"(r[2]), "=r"(r[3]) : "r"(addr));
}
__device__ __forceinline__ uint32_t pack_bf16x2(float lo, float hi) {
    uint32_t r;
    asm("cvt.rn.bf16x2.f32 %0, %1, %2;" : "=r"(r) : "f"(hi), "f"(lo));
    return r;
}
__device__ __forceinline__ void split2(float p0, float p1, uint32_t& h, uint32_t& l) {
    h = pack_bf16x2(p0, p1);
    __nv_bfloat162 hv = *reinterpret_cast<__nv_bfloat162*>(&h);
    l = pack_bf16x2(p0 - __bfloat162float(hv.x), p1 - __bfloat162float(hv.y));
}

// ---------------- Kernel 0: fp32 -> bf16 hi/lo split ----------------
__global__ __launch_bounds__(256) void split_x(const float* __restrict__ src)
{
    int i = blockIdx.x * blockDim.x + threadIdx.x;
    float4 v = *(const float4*)(src + 4*i);
    __nv_bfloat16 h0 = __float2bfloat16_rn(v.x), h1 = __float2bfloat16_rn(v.y);
    __nv_bfloat16 h2 = __float2bfloat16_rn(v.z), h3 = __float2bfloat16_rn(v.w);
    __nv_bfloat16 l0 = __float2bfloat16_rn(v.x - __bfloat162float(h0));
    __nv_bfloat16 l1 = __float2bfloat16_rn(v.y - __bfloat162float(h1));
    __nv_bfloat16 l2 = __float2bfloat16_rn(v.z - __bfloat162float(h2));
    __nv_bfloat16 l3 = __float2bfloat16_rn(v.w - __bfloat162float(h3));
    ((__nv_bfloat162*)g_Xhi)[2*i]   = __nv_bfloat162(h0, h1);
    ((__nv_bfloat162*)g_Xhi)[2*i+1] = __nv_bfloat162(h2, h3);
    ((__nv_bfloat162*)g_Xlo)[2*i]   = __nv_bfloat162(l0, l1);
    ((__nv_bfloat162*)g_Xlo)[2*i+1] = __nv_bfloat162(l2, l3);
}
__global__ __launch_bounds__(256) void split_w3(const float* __restrict__ Wq,
                                                const float* __restrict__ Wk,
                                                const float* __restrict__ Wv)
{
    int mat = blockIdx.y;
    const float* __restrict__ src = (mat == 0) ? Wq : ((mat == 1) ? Wk : Wv);
    int i = blockIdx.x * blockDim.x + threadIdx.x;
    size_t base = (size_t)mat * HD * HD / 2;
    float4 v = *(const float4*)(src + 4*i);
    __nv_bfloat16 h0 = __float2bfloat16_rn(v.x), h1 = __float2bfloat16_rn(v.y);
    __nv_bfloat16 h2 = __float2bfloat16_rn(v.z), h3 = __float2bfloat16_rn(v.w);
    __nv_bfloat16 l0 = __float2bfloat16_rn(v.x - __bfloat162float(h0));
    __nv_bfloat16 l1 = __float2bfloat16_rn(v.y - __bfloat162float(h1));
    __nv_bfloat16 l2 = __float2bfloat16_rn(v.z - __bfloat162float(h2));
    __nv_bfloat16 l3 = __float2bfloat16_rn(v.w - __bfloat162float(h3));
    ((__nv_bfloat162*)g_Whi)[base + 2*i]   = __nv_bfloat162(h0, h1);
    ((__nv_bfloat162*)g_Whi)[base + 2*i+1] = __nv_bfloat162(h2, h3);
    ((__nv_bfloat162*)g_Wlo)[base + 2*i]   = __nv_bfloat162(l0, l1);
    ((__nv_bfloat162*)g_Wlo)[base + 2*i+1] = __nv_bfloat162(l2, l3);
}

// ---------------- Kernel 1: QKV GEMM via mma.sync + ldmatrix ----------------
#define KS 32
#define NST (HD/KS)
#define ARRB (128*80)
#define STAGEB (4*ARRB)

__global__ __launch_bounds__(256, 2) void qkv_mma()
{
    extern __shared__ char smem[];
    const int t = threadIdx.x, lane = t & 31, wid = t >> 5;
    const int wm = wid & 1, wn = wid >> 1;
    const int g = lane >> 2, qd = lane & 3;
    const int mat = blockIdx.z;
    const int m0 = blockIdx.y * 128, n0 = blockIdx.x * 128;
    const __nv_bfloat16* __restrict__ Bhp = g_Whi + (size_t)mat * HD * HD;
    const __nv_bfloat16* __restrict__ Blp = g_Wlo + (size_t)mat * HD * HD;
    uint32_t sb = smem_u32(smem);

    float acc[4][4][4] = {};

    const uint32_t arow_off = (uint32_t)((wm*64 + (lane & 15)) * 80 + (lane >> 4) * 16);
    const uint32_t brow_off = (uint32_t)((wn*32 + (lane & 7) + ((lane >> 4) << 3)) * 80
                                         + ((lane >> 3) & 1) * 16);

    auto stage = [&](int s, int bsel) {
        int kt = s * KS;
        uint32_t base = sb + bsel * STAGEB;
        #pragma unroll
        for (int i = 0; i < 2; i++) {
            int c = t + i * 256;
            int row = c >> 2, seg = c & 3;
            uint32_t so = row * 80 + seg * 16;
            size_t ga = (size_t)(m0 + row) * HD + kt + seg * 8;
            size_t gb = (size_t)(n0 + row) * HD + kt + seg * 8;
            cp16(base + so,          g_Xhi + ga);
            cp16(base + ARRB + so,   g_Xlo + ga);
            cp16(base + 2*ARRB + so, Bhp + gb);
            cp16(base + 3*ARRB + so, Blp + gb);
        }
        asm volatile("cp.async.commit_group;" ::: "memory");
    };

    stage(0, 0);
    int buf = 0;
    for (int s = 0; s < NST; s++) {
        if (s + 1 < NST) {
            stage(s + 1, buf ^ 1);
            asm volatile("cp.async.wait_group 1;" ::: "memory");
        } else {
            asm volatile("cp.async.wait_group 0;" ::: "memory");
        }
        __syncthreads();

        uint32_t sbase = sb + buf * STAGEB;
        #pragma unroll
        for (int ks = 0; ks < 2; ks++) {
            uint32_t bh4[2][4], bl4[2][4];
            #pragma unroll
            for (int ntp = 0; ntp < 2; ntp++) {
                uint32_t baddr = sbase + 2*ARRB + brow_off + ntp*(16*80) + ks*32;
                ldm_x4(bh4[ntp], baddr);
                ldm_x4(bl4[ntp], baddr + ARRB);
            }
            #pragma unroll
            for (int mt = 0; mt < 4; mt++) {
                uint32_t aaddr = sbase + arow_off + mt*(16*80) + ks*32;
                uint32_t ah[4], al[4];
                ldm_x4(ah, aaddr);
                ldm_x4(al, aaddr + ARRB);
                #pragma unroll
                for (int nt = 0; nt < 4; nt++) {
                    uint32_t b0 = bh4[nt>>1][(nt&1)*2], b1 = bh4[nt>>1][(nt&1)*2+1];
                    uint32_t c0 = bl4[nt>>1][(nt&1)*2], c1 = bl4[nt>>1][(nt&1)*2+1];
                    mma16816(acc[mt][nt], ah[0],ah[1],ah[2],ah[3], b0, b1);
                    mma16816(acc[mt][nt], al[0],al[1],al[2],al[3], b0, b1);
                    mma16816(acc[mt][nt], ah[0],ah[1],ah[2],ah[3], c0, c1);
                }
            }
        }
        __syncthreads();
        buf ^= 1;
    }

    if (mat == 2) {
        #pragma unroll
        for (int mt = 0; mt < 4; mt++) {
            int r = m0 + wm*64 + mt*16 + g;
            #pragma unroll
            for (int nt = 0; nt < 4; nt++) {
                int c = n0 + wn*32 + nt*8 + 2*qd;
                *(float2*)&g_V[(size_t)r*HD + c]     = make_float2(acc[mt][nt][0], acc[mt][nt][1]);
                *(float2*)&g_V[(size_t)(r+8)*HD + c] = make_float2(acc[mt][nt][2], acc[mt][nt][3]);
            }
        }
    } else {
        __nv_bfloat16* Hp = mat ? g_Khi : g_Qhi;
        __nv_bfloat16* Lp = mat ? g_Klo : g_Qlo;
        #pragma unroll
        for (int mt = 0; mt < 4; mt++) {
            int r = m0 + wm*64 + mt*16 + g;
            #pragma unroll
            for (int nt = 0; nt < 4; nt++) {
                int c = n0 + wn*32 + nt*8 + 2*qd;
                #pragma unroll
                for (int half = 0; half < 2; half++) {
                    float v0 = acc[mt][nt][2*half], v1 = acc[mt][nt][2*half+1];
                    __nv_bfloat16 h0 = __float2bfloat16_rn(v0);
                    __nv_bfloat16 h1 = __float2bfloat16_rn(v1);
                    __nv_bfloat16 l0 = __float2bfloat16_rn(v0 - __bfloat162float(h0));
                    __nv_bfloat16 l1 = __float2bfloat16_rn(v1 - __bfloat162float(h1));
                    size_t off = (size_t)(r + 8*half)*HD + c;
                    *(__nv_bfloat162*)&Hp[off] = __nv_bfloat162(h0, h1);
                    *(__nv_bfloat162*)&Lp[off] = __nv_bfloat162(l0, l1);
                }
            }
        }
    }
}

// ---------------- Kernel 2: db4 DWT; cA -> out, cD -> transposed bf16 hi/lo ----------------
#define DW_SV 0
#define DW_CDH 4224
#define DW_CDL 25024
#define DWT_SMEM 45824

__global__ __launch_bounds__(256) void dwt_kernel(float* __restrict__ outA)
{
    extern __shared__ char dsm[];
    float* sv = (float*)(dsm + DW_SV);
    const int t = threadIdx.x, warp = t >> 5, lane = t & 31;
    const int bh = blockIdx.y, sblk = blockIdx.x;
    const int b = bh >> 3, h = bh & 7;

    for (int i = t; i < 845; i += 256) {
        ((uint32_t*)(dsm + DW_CDH + 67*260))[i] = 0;
        ((uint32_t*)(dsm + DW_CDL + 67*260))[i] = 0;
    }

    for (int iter = 0; iter < 16; iter++) {
        int sl = iter*8 + warp;
        int s  = sblk*128 + sl;
        int rid = bh*SS + s;
        float4 v4 = *(const float4*)&g_V[(size_t)(b*SS + s)*HD + h*DK + lane*4];
        *(float4*)&sv[warp*132 + lane*4] = v4;
        __syncwarp();
        #pragma unroll
        for (int jj = 0; jj < 3; jj++) {
            int j = lane + jj*32;
            if (j < WA) {
                float alo = 0.f, ahi = 0.f;
                #pragma unroll
                for (int tt = 0; tt < 8; tt++) {
                    int i2 = 2*j + tt;
                    int vi = (i2 <= 5) ? (5 - i2) : ((i2 <= 133) ? (i2 - 6) : (261 - i2));
                    float e = sv[warp*132 + vi];
                    alo += e * REV_LO[tt];
                    ahi += e * REV_HI[tt];
                }
                outA[(size_t)rid*WA + j] = alo;
                __nv_bfloat16 hv = __float2bfloat16_rn(ahi);
                __nv_bfloat16 lv = __float2bfloat16_rn(ahi - __bfloat162float(hv));
                *(__nv_bfloat16*)(dsm + DW_CDH + j*260 + sl*2) = hv;
                *(__nv_bfloat16*)(dsm + DW_CDL + j*260 + sl*2) = lv;
            }
        }
        __syncwarp();
    }
    __syncthreads();

    const size_t gbase = ((size_t)bh*80*SS + (size_t)sblk*128) >> 1;
    for (int i = t; i < 80*64; i += 256) {
        int w = i >> 6, c = i & 63;
        uint32_t vh = *(uint32_t*)(dsm + DW_CDH + w*260 + c*4);
        uint32_t vl = *(uint32_t*)(dsm + DW_CDL + w*260 + c*4);
        ((uint32_t*)g_cDh)[gbase + (size_t)w*(SS/2) + c] = vh;
        ((uint32_t*)g_cDl)[gbase + (size_t)w*(SS/2) + c] = vl;
    }
}

// ---------------- Kernel 3: flash attention, Q-tile 128, double-buffered ----------------
// smem: QH 0, QL 34816 (128 x 272B rows each);
//       2 stages @69632 + s*57856: KH +0, KL +17408 (64x272B), CDH +34816, CDL +46336 (80x144B)
//       stats @185344: sm_mx[2][128], sm_sum[2][128].  Obuf overlays stage 0.
#define AQH 0
#define AQL 34816
#define ASTG 69632
#define STG_SZ 57856
#define SKH 0
#define SKL 17408
#define SCDH 34816
#define SCDL 46336
#define ASTAT 185344
#define ATTN_SMEM (ASTAT + 2048)
#define AOBUF ASTG

__global__ __launch_bounds__(256, 1) void attn_kernel(float* __restrict__ out1)
{
    extern __shared__ char smem[];
    uint32_t sb = smem_u32(smem);
    float* sm_mx  = (float*)(smem + ASTAT);     // [2][128]
    float* sm_sum = sm_mx + 256;                // [2][128]

    const int t = threadIdx.x;
    const int lane = t & 31, wid = t >> 5;
    const int g = lane >> 2, qd = lane & 3;
    const int qg = wid >> 1, kh = wid & 1;      // warp = (32-query group, key-half)
    const int bh = blockIdx.y;
    const int b  = bh >> 3;
    const int h  = bh & 7;
    const int q0 = blockIdx.x * 128;

    // load Q tiles (hi/lo), 128 rows
    for (int i = t; i < 128*16; i += 256) {
        int row = i >> 4, seg = i & 15;
        size_t go = (size_t)(b*SS + q0 + row)*HD + h*DK + seg*8;
        *(uint4*)(smem + AQH + row*272 + seg*16) = *(const uint4*)(g_Qhi + go);
        *(uint4*)(smem + AQL + row*272 + seg*16) = *(const uint4*)(g_Qlo + go);
    }

    float O[2][10][4] = {};
    float mm[2][2] = {{-1e30f,-1e30f},{-1e30f,-1e30f}};
    float ll[2][2] = {{0.f,0.f},{0.f,0.f}};

    const uint32_t qfoff = (uint32_t)((qg*32 + (lane & 15))*272 + (lane >> 4)*16);
    const uint32_t kfoff = (uint32_t)((kh*32 + (lane & 7) + ((lane >> 4) << 3))*272
                                     + ((lane >> 3) & 1)*16);
    const uint32_t cfoff = (uint32_t)(((lane & 7) + ((lane >> 4) << 3))*144
                                     + ((lane >> 3) & 1)*16 + kh*64);

    auto load_chunk = [&](int k0c, int stg) {
        uint32_t base = sb + ASTG + stg*STG_SZ;
        for (int i = t; i < 64*16; i += 256) {
            int row = i >> 4, seg = i & 15;
            size_t go = (size_t)(b*SS + k0c + row)*HD + h*DK + seg*8;
            cp16(base + SKH + row*272 + seg*16, g_Khi + go);
            cp16(base + SKL + row*272 + seg*16, g_Klo + go);
        }
        for (int i = t; i < 80*8; i += 256) {
            int w = i >> 3, c = i & 7;
            size_t go = (size_t)(bh*80 + w)*SS + k0c + c*8;
            cp16(base + SCDH + w*144 + c*16, g_cDh + go);
            cp16(base + SCDL + w*144 + c*16, g_cDl + go);
        }
        asm volatile("cp.async.commit_group;" ::: "memory");
    };

    load_chunk(0, 0);
    __syncthreads();   // Q visible + stage-0 issue done

    int stg = 0;
    for (int k0c = 0; k0c < SS; k0c += 64) {
        if (k0c + 64 < SS) {
            load_chunk(k0c + 64, stg ^ 1);
            asm volatile("cp.async.wait_group 1;" ::: "memory");
        } else {
            asm volatile("cp.async.wait_group 0;" ::: "memory");
        }
        __syncthreads();

        uint32_t sbase = sb + ASTG + stg*STG_SZ;
        uint32_t qb  = sb + AQH + qfoff;
        uint32_t kbs = sbase + SKH + kfoff;
        uint32_t cbs = sbase + SCDH + cfoff;

        // -------- Phase A: S (32q x 32k) in registers --------
        float acc[2][4][4] = {};
        #pragma unroll
        for (int kb = 0; kb < 8; kb++) {
            uint32_t b0h[4], b1h[4], b0l[4], b1l[4];
            ldm_x4(b0h, kbs + kb*32);
            ldm_x4(b1h, kbs + kb*32 + 16*272);
            ldm_x4(b0l, kbs + kb*32 + 17408);
            ldm_x4(b1l, kbs + kb*32 + 16*272 + 17408);
            #pragma unroll
            for (int qs = 0; qs < 2; qs++) {
                uint32_t ah[4], al[4];
                uint32_t qa = qb + qs*(16*272) + kb*32;
                ldm_x4(ah, qa);
                ldm_x4(al, qa + 34816);
                #pragma unroll
                for (int nt = 0; nt < 4; nt++) {
                    uint32_t h0 = (nt < 2) ? b0h[(nt&1)*2]   : b1h[(nt&1)*2];
                    uint32_t h1 = (nt < 2) ? b0h[(nt&1)*2+1] : b1h[(nt&1)*2+1];
                    uint32_t c0 = (nt < 2) ? b0l[(nt&1)*2]   : b1l[(nt&1)*2];
                    uint32_t c1 = (nt < 2) ? b0l[(nt&1)*2+1] : b1l[(nt&1)*2+1];
                    mma16816(acc[qs][nt], ah[0],ah[1],ah[2],ah[3], h0, h1);
                    mma16816(acc[qs][nt], al[0],al[1],al[2],al[3], h0, h1);
                    mma16816(acc[qs][nt], ah[0],ah[1],ah[2],ah[3], c0, c1);
                }
            }
        }

        // -------- Phase B: softmax in registers --------
        float mnew[2][2], fac[2][2];
        #pragma unroll
        for (int qs = 0; qs < 2; qs++) {
            #pragma unroll
            for (int nt = 0; nt < 4; nt++)
                #pragma unroll
                for (int i2 = 0; i2 < 4; i2++) acc[qs][nt][i2] *= SCALE;
            float mx0 = -1e30f, mx1 = -1e30f;
            #pragma unroll
            for (int nt = 0; nt < 4; nt++) {
                mx0 = fmaxf(mx0, fmaxf(acc[qs][nt][0], acc[qs][nt][1]));
                mx1 = fmaxf(mx1, fmaxf(acc[qs][nt][2], acc[qs][nt][3]));
            }
            mx0 = fmaxf(mx0, __shfl_xor_sync(0xffffffffu, mx0, 1));
            mx0 = fmaxf(mx0, __shfl_xor_sync(0xffffffffu, mx0, 2));
            mx1 = fmaxf(mx1, __shfl_xor_sync(0xffffffffu, mx1, 1));
            mx1 = fmaxf(mx1, __shfl_xor_sync(0xffffffffu, mx1, 2));
            if (qd == 0) {
                sm_mx[kh*128 + qg*32 + qs*16 + g]     = mx0;
                sm_mx[kh*128 + qg*32 + qs*16 + g + 8] = mx1;
            }
        }
        __syncthreads();
        #pragma unroll
        for (int qs = 0; qs < 2; qs++) {
            int r0 = qg*32 + qs*16 + g, r1 = r0 + 8;
            mnew[qs][0] = fmaxf(mm[qs][0], fmaxf(sm_mx[r0], sm_mx[128 + r0]));
            mnew[qs][1] = fmaxf(mm[qs][1], fmaxf(sm_mx[r1], sm_mx[128 + r1]));
            fac[qs][0] = __expf(mm[qs][0] - mnew[qs][0]);
            fac[qs][1] = __expf(mm[qs][1] - mnew[qs][1]);
            float sum0 = 0.f, sum1 = 0.f;
            #pragma unroll
            for (int nt = 0; nt < 4; nt++) {
                acc[qs][nt][0] = __expf(acc[qs][nt][0] - mnew[qs][0]);
                acc[qs][nt][1] = __expf(acc[qs][nt][1] - mnew[qs][0]);
                acc[qs][nt][2] = __expf(acc[qs][nt][2] - mnew[qs][1]);
                acc[qs][nt][3] = __expf(acc[qs][nt][3] - mnew[qs][1]);
                sum0 += acc[qs][nt][0] + acc[qs][nt][1];
                sum1 += acc[qs][nt][2] + acc[qs][nt][3];
            }
            sum0 += __shfl_xor_sync(0xffffffffu, sum0, 1);
            sum0 += __shfl_xor_sync(0xffffffffu, sum0, 2);
            sum1 += __shfl_xor_sync(0xffffffffu, sum1, 1);
            sum1 += __shfl_xor_sync(0xffffffffu, sum1, 2);
            if (qd == 0) {
                sm_sum[kh*128 + r0] = sum0;
                sm_sum[kh*128 + r1] = sum1;
            }
            mm[qs][0] = mnew[qs][0]; mm[qs][1] = mnew[qs][1];
        }
        __syncthreads();

        // -------- Phase C: per qsub, O = O*fac + P @ cD^T --------
        #pragma unroll
        for (int qs = 0; qs < 2; qs++) {
            int r0 = qg*32 + qs*16 + g, r1 = r0 + 8;
            ll[qs][0] = ll[qs][0]*fac[qs][0] + sm_sum[r0] + sm_sum[128 + r0];
            ll[qs][1] = ll[qs][1]*fac[qs][1] + sm_sum[r1] + sm_sum[128 + r1];

            uint32_t pah[2][4], pal[2][4];
            #pragma unroll
            for (int kbi = 0; kbi < 2; kbi++) {
                int na = 2*kbi, nb = na + 1;
                split2(acc[qs][na][0], acc[qs][na][1], pah[kbi][0], pal[kbi][0]);
                split2(acc[qs][na][2], acc[qs][na][3], pah[kbi][1], pal[kbi][1]);
                split2(acc[qs][nb][0], acc[qs][nb][1], pah[kbi][2], pal[kbi][2]);
                split2(acc[qs][nb][2], acc[qs][nb][3], pah[kbi][3], pal[kbi][3]);
            }
            #pragma unroll
            for (int nt = 0; nt < 10; nt++) {
                O[qs][nt][0] *= fac[qs][0]; O[qs][nt][1] *= fac[qs][0];
                O[qs][nt][2] *= fac[qs][1]; O[qs][nt][3] *= fac[qs][1];
            }
            #pragma unroll
            for (int kbi = 0; kbi < 2; kbi++) {
                #pragma unroll
                for (int ntp = 0; ntp < 5; ntp++) {
                    uint32_t cb[4], cl[4];
                    uint32_t ca = cbs + ntp*(16*144) + kbi*32;
                    ldm_x4(cb, ca);
                    ldm_x4(cl, ca + 11520);
                    mma16816(O[qs][2*ntp],   pah[kbi][0],pah[kbi][1],pah[kbi][2],pah[kbi][3], cb[0], cb[1]);
                    mma16816(O[qs][2*ntp],   pal[kbi][0],pal[kbi][1],pal[kbi][2],pal[kbi][3], cb[0], cb[1]);
                    mma16816(O[qs][2*ntp],   pah[kbi][0],pah[kbi][1],pah[kbi][2],pah[kbi][3], cl[0], cl[1]);
                    mma16816(O[qs][2*ntp+1], pah[kbi][0],pah[kbi][1],pah[kbi][2],pah[kbi][3], cb[2], cb[3]);
                    mma16816(O[qs][2*ntp+1], pal[kbi][0],pal[kbi][1],pal[kbi][2],pal[kbi][3], cb[2], cb[3]);
                    mma16816(O[qs][2*ntp+1], pah[kbi][0],pah[kbi][1],pah[kbi][2],pah[kbi][3], cl[2], cl[3]);
                }
            }
        }
        __syncthreads();   // protect stage buffer + stats for next iteration
        stg ^= 1;
    }

    // -------- epilogue: merge kh halves, divide by l, store --------
    float* Obuf = (float*)(smem + AOBUF);   // [128][81] f32
    if (kh == 1) {
        #pragma unroll
        for (int qs = 0; qs < 2; qs++) {
            int r0 = qg*32 + qs*16 + g, r1 = r0 + 8;
            #pragma unroll
            for (int nt = 0; nt < 10; nt++) {
                int w = nt*8 + 2*qd;
                Obuf[r0*81 + w]     = O[qs][nt][0];
                Obuf[r0*81 + w + 1] = O[qs][nt][1];
                Obuf[r1*81 + w]     = O[qs][nt][2];
                Obuf[r1*81 + w + 1] = O[qs][nt][3];
            }
        }
    }
    __syncthreads();
    if (kh == 0) {
        #pragma unroll
        for (int qs = 0; qs < 2; qs++) {
            int r0 = qg*32 + qs*16 + g, r1 = r0 + 8;
            float li0 = 1.f / ll[qs][0], li1 = 1.f / ll[qs][1];
            int qa = q0 + r0, qb2 = q0 + r1;
            #pragma unroll
            for (int nt = 0; nt < 10; nt++) {
                int w = nt*8 + 2*qd;
                if (w < WA) {
                    out1[(size_t)(b*SS + qa)*OW + h*WA + w]  = (O[qs][nt][0] + Obuf[r0*81 + w])*li0;
                    out1[(size_t)(b*SS + qb2)*OW + h*WA + w] = (O[qs][nt][2] + Obuf[r1*81 + w])*li1;
                }
                if (w + 1 < WA) {
                    out1[(size_t)(b*SS + qa)*OW + h*WA + w + 1]  = (O[qs][nt][1] + Obuf[r0*81 + w + 1])*li0;
                    out1[(size_t)(b*SS + qb2)*OW + h*WA + w + 1] = (O[qs][nt][3] + Obuf[r1*81 + w + 1])*li1;
                }
            }
        }
    }
}

// ---------------- launch ----------------
extern "C" void kernel_launch(void* const* d_in, const int* in_sizes, int n_in,
                              void* d_out, int out_size)
{
    const float* x  = (const float*)d_in[0];
    const float* Wq = (const float*)d_in[1];
    const float* Wk = (const float*)d_in[2];
    const float* Wv = (const float*)d_in[3];
    float* out = (float*)d_out;

    (void)in_sizes; (void)n_in; (void)out_size;

    split_x<<<(BB*SS*HD/4 + 255)/256, 256>>>(x);
    split_w3<<<dim3(HD*HD/4/256, 3), 256>>>(Wq, Wk, Wv);

    cudaFuncSetAttribute(qkv_mma, cudaFuncAttributeMaxDynamicSharedMemorySize, 2*STAGEB);
    qkv_mma<<<dim3(HD/128, (BB*SS)/128, 3), 256, 2*STAGEB>>>();

    cudaFuncSetAttribute(dwt_kernel, cudaFuncAttributeMaxDynamicSharedMemorySize, DWT_SMEM);
    dwt_kernel<<<dim3(SS/128, BH), 256, DWT_SMEM>>>(out + OUT1_ELEMS);

    cudaFuncSetAttribute(attn_kernel, cudaFuncAttributeMaxDynamicSharedMemorySize, ATTN_SMEM);
    attn_kernel<<<dim3(SS/128, BH), 256, ATTN_SMEM>>>(out);
}

// round 11
// speedup vs baseline: 1.0542x; 1.0542x over previous
#include <cuda_runtime.h>
#include <cuda_bf16.h>
#include <math.h>
#include <stdint.h>

#define BB 4
#define SS 2048
#define HD 1024
#define NH 8
#define DK 128
#define WA 67
#define BH (BB*NH)
#define NROWS (BH*SS)
#define OUT1_ELEMS (BB*SS*NH*WA)
#define OW (NH*WA)
#define SCALE 0.08838834764831845f

// ---------------- scratch (device globals; no allocation allowed) ----------------
__device__ float g_V[BB*SS*HD];
__device__ __nv_bfloat16 g_cDh[BH*80*SS];     // transposed: [bh][w(80, zero-padded)][s]
__device__ __nv_bfloat16 g_cDl[BH*80*SS];
__device__ __nv_bfloat16 g_Xhi[BB*SS*HD];
__device__ __nv_bfloat16 g_Xlo[BB*SS*HD];
__device__ __nv_bfloat16 g_Whi[3*HD*HD];
__device__ __nv_bfloat16 g_Wlo[3*HD*HD];
__device__ __nv_bfloat16 g_Qhi[BB*SS*HD];     // pre-scaled by SCALE
__device__ __nv_bfloat16 g_Qlo[BB*SS*HD];
__device__ __nv_bfloat16 g_Khi[BB*SS*HD];
__device__ __nv_bfloat16 g_Klo[BB*SS*HD];

// db4 filters, pre-reversed:  g[t] = DEC[7-t]
__constant__ float REV_LO[8] = {
    0.23037781330885523f,  0.7148465705525415f,   0.6308807679295904f,
   -0.02798376941698385f, -0.18703481171888114f,  0.030841381835986965f,
    0.032883011666982945f,-0.010597401784997278f };
__constant__ float REV_HI[8] = {
   -0.010597401784997278f,-0.032883011666982945f, 0.030841381835986965f,
    0.18703481171888114f, -0.02798376941698385f, -0.6308807679295904f,
    0.7148465705525415f,  -0.23037781330885523f };

// ---------------- helpers ----------------
__device__ __forceinline__ uint32_t smem_u32(const void* p) {
    uint32_t a;
    asm("{ .reg .u64 t; cvta.to.shared.u64 t, %1; cvt.u32.u64 %0, t; }" : "=r"(a) : "l"(p));
    return a;
}
__device__ __forceinline__ void cp16(uint32_t s, const void* g) {
    asm volatile("cp.async.cg.shared.global [%0], [%1], 16;" :: "r"(s), "l"(g));
}
__device__ __forceinline__ void mma16816(float* d,
    uint32_t a0, uint32_t a1, uint32_t a2, uint32_t a3, uint32_t b0, uint32_t b1) {
    asm volatile(
        "mma.sync.aligned.m16n8k16.row.col.f32.bf16.bf16.f32 "
        "{%0,%1,%2,%3}, {%4,%5,%6,%7}, {%8,%9}, {%0,%1,%2,%3};"
        : "+f"(d[0]), "+f"(d[1]), "+f"(d[2]), "+f"(d[3])
        : "r"(a0), "r"(a1), "r"(a2), "r"(a3), "r"(b0), "r"(b1));
}
__device__ __forceinline__ void ldm_x4(uint32_t* r, uint32_t addr) {
    asm volatile("ldmatrix.sync.aligned.m8n8.x4.shared.b16 {%0,%1,%2,%3}, [%4];"
        : "=r"(r[0]), "=r"(r[1]), "=r"(r[2]), "=r"(r[3]) : "r"(addr));
}
__device__ __forceinline__ uint32_t pack_bf16x2(float lo, float hi) {
    uint32_t r;
    asm("cvt.rn.bf16x2.f32 %0, %1, %2;" : "=r"(r) : "f"(hi), "f"(lo));
    return r;
}
__device__ __forceinline__ void split2(float p0, float p1, uint32_t& h, uint32_t& l) {
    h = pack_bf16x2(p0, p1);
    __nv_bfloat162 hv = *reinterpret_cast<__nv_bfloat162*>(&h);
    l = pack_bf16x2(p0 - __bfloat162float(hv.x), p1 - __bfloat162float(hv.y));
}
__device__ __forceinline__ void bar_pair(int id) {
    asm volatile("bar.sync %0, 64;" :: "r"(id) : "memory");
}

// ---------------- Kernel 0: fp32 -> bf16 hi/lo split ----------------
__global__ __launch_bounds__(256) void split_x(const float* __restrict__ src)
{
    int i = blockIdx.x * blockDim.x + threadIdx.x;
    float4 v = *(const float4*)(src + 4*i);
    __nv_bfloat16 h0 = __float2bfloat16_rn(v.x), h1 = __float2bfloat16_rn(v.y);
    __nv_bfloat16 h2 = __float2bfloat16_rn(v.z), h3 = __float2bfloat16_rn(v.w);
    __nv_bfloat16 l0 = __float2bfloat16_rn(v.x - __bfloat162float(h0));
    __nv_bfloat16 l1 = __float2bfloat16_rn(v.y - __bfloat162float(h1));
    __nv_bfloat16 l2 = __float2bfloat16_rn(v.z - __bfloat162float(h2));
    __nv_bfloat16 l3 = __float2bfloat16_rn(v.w - __bfloat162float(h3));
    ((__nv_bfloat162*)g_Xhi)[2*i]   = __nv_bfloat162(h0, h1);
    ((__nv_bfloat162*)g_Xhi)[2*i+1] = __nv_bfloat162(h2, h3);
    ((__nv_bfloat162*)g_Xlo)[2*i]   = __nv_bfloat162(l0, l1);
    ((__nv_bfloat162*)g_Xlo)[2*i+1] = __nv_bfloat162(l2, l3);
}
__global__ __launch_bounds__(256) void split_w3(const float* __restrict__ Wq,
                                                const float* __restrict__ Wk,
                                                const float* __restrict__ Wv)
{
    int mat = blockIdx.y;
    const float* __restrict__ src = (mat == 0) ? Wq : ((mat == 1) ? Wk : Wv);
    int i = blockIdx.x * blockDim.x + threadIdx.x;
    size_t base = (size_t)mat * HD * HD / 2;
    float4 v = *(const float4*)(src + 4*i);
    __nv_bfloat16 h0 = __float2bfloat16_rn(v.x), h1 = __float2bfloat16_rn(v.y);
    __nv_bfloat16 h2 = __float2bfloat16_rn(v.z), h3 = __float2bfloat16_rn(v.w);
    __nv_bfloat16 l0 = __float2bfloat16_rn(v.x - __bfloat162float(h0));
    __nv_bfloat16 l1 = __float2bfloat16_rn(v.y - __bfloat162float(h1));
    __nv_bfloat16 l2 = __float2bfloat16_rn(v.z - __bfloat162float(h2));
    __nv_bfloat16 l3 = __float2bfloat16_rn(v.w - __bfloat162float(h3));
    ((__nv_bfloat162*)g_Whi)[base + 2*i]   = __nv_bfloat162(h0, h1);
    ((__nv_bfloat162*)g_Whi)[base + 2*i+1] = __nv_bfloat162(h2, h3);
    ((__nv_bfloat162*)g_Wlo)[base + 2*i]   = __nv_bfloat162(l0, l1);
    ((__nv_bfloat162*)g_Wlo)[base + 2*i+1] = __nv_bfloat162(l2, l3);
}

// ---------------- Kernel 1: QKV GEMM via mma.sync + ldmatrix ----------------
#define KS 32
#define NST (HD/KS)
#define ARRB (128*80)
#define STAGEB (4*ARRB)

__global__ __launch_bounds__(256, 2) void qkv_mma()
{
    extern __shared__ char smem[];
    const int t = threadIdx.x, lane = t & 31, wid = t >> 5;
    const int wm = wid & 1, wn = wid >> 1;
    const int g = lane >> 2, qd = lane & 3;
    const int mat = blockIdx.z;
    const int m0 = blockIdx.y * 128, n0 = blockIdx.x * 128;
    const __nv_bfloat16* __restrict__ Bhp = g_Whi + (size_t)mat * HD * HD;
    const __nv_bfloat16* __restrict__ Blp = g_Wlo + (size_t)mat * HD * HD;
    uint32_t sb = smem_u32(smem);

    float acc[4][4][4] = {};

    const uint32_t arow_off = (uint32_t)((wm*64 + (lane & 15)) * 80 + (lane >> 4) * 16);
    const uint32_t brow_off = (uint32_t)((wn*32 + (lane & 7) + ((lane >> 4) << 3)) * 80
                                         + ((lane >> 3) & 1) * 16);

    auto stage = [&](int s, int bsel) {
        int kt = s * KS;
        uint32_t base = sb + bsel * STAGEB;
        #pragma unroll
        for (int i = 0; i < 2; i++) {
            int c = t + i * 256;
            int row = c >> 2, seg = c & 3;
            uint32_t so = row * 80 + seg * 16;
            size_t ga = (size_t)(m0 + row) * HD + kt + seg * 8;
            size_t gb = (size_t)(n0 + row) * HD + kt + seg * 8;
            cp16(base + so,          g_Xhi + ga);
            cp16(base + ARRB + so,   g_Xlo + ga);
            cp16(base + 2*ARRB + so, Bhp + gb);
            cp16(base + 3*ARRB + so, Blp + gb);
        }
        asm volatile("cp.async.commit_group;" ::: "memory");
    };

    stage(0, 0);
    int buf = 0;
    for (int s = 0; s < NST; s++) {
        if (s + 1 < NST) {
            stage(s + 1, buf ^ 1);
            asm volatile("cp.async.wait_group 1;" ::: "memory");
        } else {
            asm volatile("cp.async.wait_group 0;" ::: "memory");
        }
        __syncthreads();

        uint32_t sbase = sb + buf * STAGEB;
        #pragma unroll
        for (int ks = 0; ks < 2; ks++) {
            uint32_t bh4[2][4], bl4[2][4];
            #pragma unroll
            for (int ntp = 0; ntp < 2; ntp++) {
                uint32_t baddr = sbase + 2*ARRB + brow_off + ntp*(16*80) + ks*32;
                ldm_x4(bh4[ntp], baddr);
                ldm_x4(bl4[ntp], baddr + ARRB);
            }
            #pragma unroll
            for (int mt = 0; mt < 4; mt++) {
                uint32_t aaddr = sbase + arow_off + mt*(16*80) + ks*32;
                uint32_t ah[4], al[4];
                ldm_x4(ah, aaddr);
                ldm_x4(al, aaddr + ARRB);
                #pragma unroll
                for (int nt = 0; nt < 4; nt++) {
                    uint32_t b0 = bh4[nt>>1][(nt&1)*2], b1 = bh4[nt>>1][(nt&1)*2+1];
                    uint32_t c0 = bl4[nt>>1][(nt&1)*2], c1 = bl4[nt>>1][(nt&1)*2+1];
                    mma16816(acc[mt][nt], ah[0],ah[1],ah[2],ah[3], b0, b1);
                    mma16816(acc[mt][nt], al[0],al[1],al[2],al[3], b0, b1);
                    mma16816(acc[mt][nt], ah[0],ah[1],ah[2],ah[3], c0, c1);
                }
            }
        }
        __syncthreads();
        buf ^= 1;
    }

    if (mat == 2) {
        #pragma unroll
        for (int mt = 0; mt < 4; mt++) {
            int r = m0 + wm*64 + mt*16 + g;
            #pragma unroll
            for (int nt = 0; nt < 4; nt++) {
                int c = n0 + wn*32 + nt*8 + 2*qd;
                *(float2*)&g_V[(size_t)r*HD + c]     = make_float2(acc[mt][nt][0], acc[mt][nt][1]);
                *(float2*)&g_V[(size_t)(r+8)*HD + c] = make_float2(acc[mt][nt][2], acc[mt][nt][3]);
            }
        }
    } else {
        __nv_bfloat16* Hp = mat ? g_Khi : g_Qhi;
        __nv_bfloat16* Lp = mat ? g_Klo : g_Qlo;
        const float sc = mat ? 1.0f : SCALE;    // fold softmax scale into Q
        #pragma unroll
        for (int mt = 0; mt < 4; mt++) {
            int r = m0 + wm*64 + mt*16 + g;
            #pragma unroll
            for (int nt = 0; nt < 4; nt++) {
                int c = n0 + wn*32 + nt*8 + 2*qd;
                #pragma unroll
                for (int half = 0; half < 2; half++) {
                    float v0 = acc[mt][nt][2*half]*sc, v1 = acc[mt][nt][2*half+1]*sc;
                    __nv_bfloat16 h0 = __float2bfloat16_rn(v0);
                    __nv_bfloat16 h1 = __float2bfloat16_rn(v1);
                    __nv_bfloat16 l0 = __float2bfloat16_rn(v0 - __bfloat162float(h0));
                    __nv_bfloat16 l1 = __float2bfloat16_rn(v1 - __bfloat162float(h1));
                    size_t off = (size_t)(r + 8*half)*HD + c;
                    *(__nv_bfloat162*)&Hp[off] = __nv_bfloat162(h0, h1);
                    *(__nv_bfloat162*)&Lp[off] = __nv_bfloat162(l0, l1);
                }
            }
        }
    }
}

// ---------------- Kernel 2: db4 DWT; cA -> out, cD -> transposed bf16 hi/lo ----------------
#define DW_SV 0
#define DW_CDH 4224
#define DW_CDL 25024
#define DWT_SMEM 45824

__global__ __launch_bounds__(256) void dwt_kernel(float* __restrict__ outA)
{
    extern __shared__ char dsm[];
    float* sv = (float*)(dsm + DW_SV);
    const int t = threadIdx.x, warp = t >> 5, lane = t & 31;
    const int bh = blockIdx.y, sblk = blockIdx.x;
    const int b = bh >> 3, h = bh & 7;

    for (int i = t; i < 845; i += 256) {
        ((uint32_t*)(dsm + DW_CDH + 67*260))[i] = 0;
        ((uint32_t*)(dsm + DW_CDL + 67*260))[i] = 0;
    }

    for (int iter = 0; iter < 16; iter++) {
        int sl = iter*8 + warp;
        int s  = sblk*128 + sl;
        int rid = bh*SS + s;
        float4 v4 = *(const float4*)&g_V[(size_t)(b*SS + s)*HD + h*DK + lane*4];
        *(float4*)&sv[warp*132 + lane*4] = v4;
        __syncwarp();
        #pragma unroll
        for (int jj = 0; jj < 3; jj++) {
            int j = lane + jj*32;
            if (j < WA) {
                float alo = 0.f, ahi = 0.f;
                #pragma unroll
                for (int tt = 0; tt < 8; tt++) {
                    int i2 = 2*j + tt;
                    int vi = (i2 <= 5) ? (5 - i2) : ((i2 <= 133) ? (i2 - 6) : (261 - i2));
                    float e = sv[warp*132 + vi];
                    alo += e * REV_LO[tt];
                    ahi += e * REV_HI[tt];
                }
                outA[(size_t)rid*WA + j] = alo;
                __nv_bfloat16 hv = __float2bfloat16_rn(ahi);
                __nv_bfloat16 lv = __float2bfloat16_rn(ahi - __bfloat162float(hv));
                *(__nv_bfloat16*)(dsm + DW_CDH + j*260 + sl*2) = hv;
                *(__nv_bfloat16*)(dsm + DW_CDL + j*260 + sl*2) = lv;
            }
        }
        __syncwarp();
    }
    __syncthreads();

    const size_t gbase = ((size_t)bh*80*SS + (size_t)sblk*128) >> 1;
    for (int i = t; i < 80*64; i += 256) {
        int w = i >> 6, c = i & 63;
        uint32_t vh = *(uint32_t*)(dsm + DW_CDH + w*260 + c*4);
        uint32_t vl = *(uint32_t*)(dsm + DW_CDL + w*260 + c*4);
        ((uint32_t*)g_cDh)[gbase + (size_t)w*(SS/2) + c] = vh;
        ((uint32_t*)g_cDl)[gbase + (size_t)w*(SS/2) + c] = vl;
    }
}

// ---------------- Kernel 3: register-resident flash attention (R9 shape, pair barriers) ----------------
// smem: QH 0, QL 17408, KH 34816, KL 52224 (64 x 272B rows);
//       CDH 69632, CDL 81152 (80 x 144B rows: [w][key]);
//       stats @92672: sm_mx[2][64], sm_sum[2][64].  Obuf overlays KH at epilogue.
#define QH_OFF 0
#define QL_OFF 17408
#define KH_OFF 34816
#define KL_OFF 52224
#define CDH_OFF 69632
#define CDL_OFF 81152
#define STAT_OFF 92672
#define ATTN_SMEM (STAT_OFF + 1024)
#define OBUF_OFF KH_OFF

__global__ __launch_bounds__(256, 2) void attn_kernel(float* __restrict__ out1)
{
    extern __shared__ char smem[];
    uint32_t sb = smem_u32(smem);
    float* sm_mx  = (float*)(smem + STAT_OFF);
    float* sm_sum = sm_mx + 128;

    const int t = threadIdx.x;
    const int lane = t & 31, wid = t >> 5;
    const int g = lane >> 2, qd = lane & 3;
    const int qg = wid >> 1, kh = wid & 1;     // warp = (query-group, key-half)
    const int bar_id = 1 + qg;                 // named barrier per warp pair
    const int bh = blockIdx.y;
    const int b  = bh >> 3;
    const int h  = bh & 7;
    const int q0 = blockIdx.x * 64;
    const int r0 = qg*16 + g, r1 = r0 + 8;

    // load Q tiles (hi/lo)
    for (int i = t; i < 64*16; i += 256) {
        int row = i >> 4, seg = i & 15;
        size_t go = (size_t)(b*SS + q0 + row)*HD + h*DK + seg*8;
        *(uint4*)(smem + QH_OFF + row*272 + seg*16) = *(const uint4*)(g_Qhi + go);
        *(uint4*)(smem + QL_OFF + row*272 + seg*16) = *(const uint4*)(g_Qlo + go);
    }

    float O[10][4] = {};
    float m0 = -1e30f, m1 = -1e30f, l0 = 0.f, l1 = 0.f;

    const uint32_t qbase = sb + QH_OFF + (uint32_t)((qg*16 + (lane & 15))*272 + (lane >> 4)*16);
    const uint32_t kbase = sb + KH_OFF
        + (uint32_t)((kh*32 + (lane & 7) + ((lane >> 4) << 3))*272 + ((lane >> 3) & 1)*16);
    const uint32_t cbase = sb + CDH_OFF
        + (uint32_t)(((lane & 7) + ((lane >> 4) << 3))*144 + ((lane >> 3) & 1)*16 + kh*64);
    __syncthreads();

    for (int k0c = 0; k0c < SS; k0c += 64) {
        // K chunk + cD chunk via cp.async
        for (int i = t; i < 64*16; i += 256) {
            int row = i >> 4, seg = i & 15;
            size_t go = (size_t)(b*SS + k0c + row)*HD + h*DK + seg*8;
            cp16(sb + KH_OFF + row*272 + seg*16, g_Khi + go);
            cp16(sb + KL_OFF + row*272 + seg*16, g_Klo + go);
        }
        for (int i = t; i < 80*8; i += 256) {
            int w = i >> 3, c = i & 7;
            size_t go = (size_t)(bh*80 + w)*SS + k0c + c*8;
            cp16(sb + CDH_OFF + w*144 + c*16, g_cDh + go);
            cp16(sb + CDL_OFF + w*144 + c*16, g_cDl + go);
        }
        asm volatile("cp.async.commit_group;" ::: "memory");
        asm volatile("cp.async.wait_group 0;" ::: "memory");
        __syncthreads();

        // -------- Phase A: S (16q x 32k) in registers --------
        float acc[4][4] = {};
        #pragma unroll
        for (int kb = 0; kb < 8; kb++) {
            uint32_t ah[4], al[4], b0h[4], b1h[4], b0l[4], b1l[4];
            ldm_x4(ah, qbase + kb*32);
            ldm_x4(al, qbase + kb*32 + (QL_OFF - QH_OFF));
            ldm_x4(b0h, kbase + kb*32);
            ldm_x4(b1h, kbase + kb*32 + 16*272);
            ldm_x4(b0l, kbase + kb*32 + (KL_OFF - KH_OFF));
            ldm_x4(b1l, kbase + kb*32 + 16*272 + (KL_OFF - KH_OFF));
            #pragma unroll
            for (int nt = 0; nt < 4; nt++) {
                uint32_t h0 = (nt < 2) ? b0h[(nt&1)*2]   : b1h[(nt&1)*2];
                uint32_t h1 = (nt < 2) ? b0h[(nt&1)*2+1] : b1h[(nt&1)*2+1];
                uint32_t c0 = (nt < 2) ? b0l[(nt&1)*2]   : b1l[(nt&1)*2];
                uint32_t c1 = (nt < 2) ? b0l[(nt&1)*2+1] : b1l[(nt&1)*2+1];
                mma16816(acc[nt], ah[0],ah[1],ah[2],ah[3], h0, h1);
                mma16816(acc[nt], al[0],al[1],al[2],al[3], h0, h1);
                mma16816(acc[nt], ah[0],ah[1],ah[2],ah[3], c0, c1);
            }
        }

        // -------- Phase B: softmax in registers (pair-barrier stats exchange) --------
        float mx0 = -1e30f, mx1 = -1e30f;
        #pragma unroll
        for (int nt = 0; nt < 4; nt++) {
            mx0 = fmaxf(mx0, fmaxf(acc[nt][0], acc[nt][1]));
            mx1 = fmaxf(mx1, fmaxf(acc[nt][2], acc[nt][3]));
        }
        mx0 = fmaxf(mx0, __shfl_xor_sync(0xffffffffu, mx0, 1));
        mx0 = fmaxf(mx0, __shfl_xor_sync(0xffffffffu, mx0, 2));
        mx1 = fmaxf(mx1, __shfl_xor_sync(0xffffffffu, mx1, 1));
        mx1 = fmaxf(mx1, __shfl_xor_sync(0xffffffffu, mx1, 2));
        if (qd == 0) { sm_mx[kh*64 + r0] = mx0; sm_mx[kh*64 + r1] = mx1; }
        bar_pair(bar_id);
        float mnew0 = fmaxf(m0, fmaxf(sm_mx[r0], sm_mx[64 + r0]));
        float mnew1 = fmaxf(m1, fmaxf(sm_mx[r1], sm_mx[64 + r1]));
        float fac0 = __expf(m0 - mnew0), fac1 = __expf(m1 - mnew1);
        float sum0 = 0.f, sum1 = 0.f;
        #pragma unroll
        for (int nt = 0; nt < 4; nt++) {
            acc[nt][0] = __expf(acc[nt][0] - mnew0);
            acc[nt][1] = __expf(acc[nt][1] - mnew0);
            acc[nt][2] = __expf(acc[nt][2] - mnew1);
            acc[nt][3] = __expf(acc[nt][3] - mnew1);
            sum0 += acc[nt][0] + acc[nt][1];
            sum1 += acc[nt][2] + acc[nt][3];
        }
        sum0 += __shfl_xor_sync(0xffffffffu, sum0, 1);
        sum0 += __shfl_xor_sync(0xffffffffu, sum0, 2);
        sum1 += __shfl_xor_sync(0xffffffffu, sum1, 1);
        sum1 += __shfl_xor_sync(0xffffffffu, sum1, 2);
        if (qd == 0) { sm_sum[kh*64 + r0] = sum0; sm_sum[kh*64 + r1] = sum1; }

        // convert P to bf16 hi/lo A-fragments while the pair barrier settles
        uint32_t pah[2][4], pal[2][4];
        #pragma unroll
        for (int kbi = 0; kbi < 2; kbi++) {
            int na = 2*kbi, nb = na + 1;
            split2(acc[na][0], acc[na][1], pah[kbi][0], pal[kbi][0]);
            split2(acc[na][2], acc[na][3], pah[kbi][1], pal[kbi][1]);
            split2(acc[nb][0], acc[nb][1], pah[kbi][2], pal[kbi][2]);
            split2(acc[nb][2], acc[nb][3], pah[kbi][3], pal[kbi][3]);
        }
        bar_pair(bar_id);
        l0 = l0*fac0 + sm_sum[r0] + sm_sum[64 + r0];
        l1 = l1*fac1 + sm_sum[r1] + sm_sum[64 + r1];
        m0 = mnew0; m1 = mnew1;

        // -------- Phase C: O = O*fac + P @ cD^T --------
        #pragma unroll
        for (int nt = 0; nt < 10; nt++) {
            O[nt][0] *= fac0; O[nt][1] *= fac0;
            O[nt][2] *= fac1; O[nt][3] *= fac1;
        }
        #pragma unroll
        for (int kbi = 0; kbi < 2; kbi++) {
            #pragma unroll
            for (int ntp = 0; ntp < 5; ntp++) {
                uint32_t cb[4], cl[4];
                uint32_t ca = cbase + ntp*(16*144) + kbi*32;
                ldm_x4(cb, ca);
                ldm_x4(cl, ca + (CDL_OFF - CDH_OFF));
                mma16816(O[2*ntp],   pah[kbi][0],pah[kbi][1],pah[kbi][2],pah[kbi][3], cb[0], cb[1]);
                mma16816(O[2*ntp],   pal[kbi][0],pal[kbi][1],pal[kbi][2],pal[kbi][3], cb[0], cb[1]);
                mma16816(O[2*ntp],   pah[kbi][0],pah[kbi][1],pah[kbi][2],pah[kbi][3], cl[0], cl[1]);
                mma16816(O[2*ntp+1], pah[kbi][0],pah[kbi][1],pah[kbi][2],pah[kbi][3], cb[2], cb[3]);
                mma16816(O[2*ntp+1], pal[kbi][0],pal[kbi][1],pal[kbi][2],pal[kbi][3], cb[2], cb[3]);
                mma16816(O[2*ntp+1], pah[kbi][0],pah[kbi][1],pah[kbi][2],pah[kbi][3], cl[2], cl[3]);
            }
        }
        __syncthreads();   // protect stage buffers for next chunk's cp.async
    }

    // -------- epilogue: merge kh halves, divide by l, store --------
    float* Obuf = (float*)(smem + OBUF_OFF);   // [64][81] f32, overlays dead K tiles
    if (kh == 1) {
        #pragma unroll
        for (int nt = 0; nt < 10; nt++) {
            int w = nt*8 + 2*qd;
            Obuf[r0*81 + w]     = O[nt][0];
            Obuf[r0*81 + w + 1] = O[nt][1];
            Obuf[r1*81 + w]     = O[nt][2];
            Obuf[r1*81 + w + 1] = O[nt][3];
        }
    }
    __syncthreads();
    if (kh == 0) {
        float li0 = 1.f / l0, li1 = 1.f / l1;
        int qa = q0 + r0, qb2 = q0 + r1;
        #pragma unroll
        for (int nt = 0; nt < 10; nt++) {
            int w = nt*8 + 2*qd;
            if (w < WA) {
                out1[(size_t)(b*SS + qa)*OW + h*WA + w]  = (O[nt][0] + Obuf[r0*81 + w])*li0;
                out1[(size_t)(b*SS + qb2)*OW + h*WA + w] = (O[nt][2] + Obuf[r1*81 + w])*li1;
            }
            if (w + 1 < WA) {
                out1[(size_t)(b*SS + qa)*OW + h*WA + w + 1]  = (O[nt][1] + Obuf[r0*81 + w + 1])*li0;
                out1[(size_t)(b*SS + qb2)*OW + h*WA + w + 1] = (O[nt][3] + Obuf[r1*81 + w + 1])*li1;
            }
        }
    }
}

// ---------------- launch ----------------
extern "C" void kernel_launch(void* const* d_in, const int* in_sizes, int n_in,
                              void* d_out, int out_size)
{
    const float* x  = (const float*)d_in[0];
    const float* Wq = (const float*)d_in[1];
    const float* Wk = (const float*)d_in[2];
    const float* Wv = (const float*)d_in[3];
    float* out = (float*)d_out;

    (void)in_sizes; (void)n_in; (void)out_size;

    split_x<<<(BB*SS*HD/4 + 255)/256, 256>>>(x);
    split_w3<<<dim3(HD*HD/4/256, 3), 256>>>(Wq, Wk, Wv);

    cudaFuncSetAttribute(qkv_mma, cudaFuncAttributeMaxDynamicSharedMemorySize, 2*STAGEB);
    qkv_mma<<<dim3(HD/128, (BB*SS)/128, 3), 256, 2*STAGEB>>>();

    cudaFuncSetAttribute(dwt_kernel, cudaFuncAttributeMaxDynamicSharedMemorySize, DWT_SMEM);
    dwt_kernel<<<dim3(SS/128, BH), 256, DWT_SMEM>>>(out + OUT1_ELEMS);

    cudaFuncSetAttribute(attn_kernel, cudaFuncAttributeMaxDynamicSharedMemorySize, ATTN_SMEM);
    attn_kernel<<<dim3(SS/64, BH), 256, ATTN_SMEM>>>(out);
}

// round 13
// speedup vs baseline: 1.0917x; 1.0356x over previous
#include <cuda_runtime.h>
#include <cuda_bf16.h>
#include <math.h>
#include <stdint.h>

#define BB 4
#define SS 2048
#define HD 1024
#define NH 8
#define DK 128
#define WA 67
#define BH (BB*NH)
#define NROWS (BH*SS)
#define OUT1_ELEMS (BB*SS*NH*WA)
#define OW (NH*WA)
#define SCALE 0.08838834764831845f
// softmax scale with log2(e) folded in (scores computed directly in log2 domain)
#define SCALE_Q (0.08838834764831845f * 1.44269504088896340736f)

// ---------------- scratch (device globals; no allocation allowed) ----------------
__device__ float g_V[BB*SS*HD];
__device__ __nv_bfloat16 g_cDh[BH*80*SS];     // transposed: [bh][w(80, zero-padded)][s]
__device__ __nv_bfloat16 g_cDl[BH*80*SS];
__device__ __nv_bfloat16 g_Xhi[BB*SS*HD];
__device__ __nv_bfloat16 g_Xlo[BB*SS*HD];
__device__ __nv_bfloat16 g_Whi[3*HD*HD];
__device__ __nv_bfloat16 g_Wlo[3*HD*HD];
__device__ __nv_bfloat16 g_Qhi[BB*SS*HD];     // pre-scaled by SCALE*log2(e)
__device__ __nv_bfloat16 g_Qlo[BB*SS*HD];
__device__ __nv_bfloat16 g_Khi[BB*SS*HD];
__device__ __nv_bfloat16 g_Klo[BB*SS*HD];

// db4 filters, pre-reversed:  g[t] = DEC[7-t]
__constant__ float REV_LO[8] = {
    0.23037781330885523f,  0.7148465705525415f,   0.6308807679295904f,
   -0.02798376941698385f, -0.18703481171888114f,  0.030841381835986965f,
    0.032883011666982945f,-0.010597401784997278f };
__constant__ float REV_HI[8] = {
   -0.010597401784997278f,-0.032883011666982945f, 0.030841381835986965f,
    0.18703481171888114f, -0.02798376941698385f, -0.6308807679295904f,
    0.7148465705525415f,  -0.23037781330885523f };

// ---------------- helpers ----------------
__device__ __forceinline__ uint32_t smem_u32(const void* p) {
    uint32_t a;
    asm("{ .reg .u64 t; cvta.to.shared.u64 t, %1; cvt.u32.u64 %0, t; }" : "=r"(a) : "l"(p));
    return a;
}
__device__ __forceinline__ void cp16(uint32_t s, const void* g) {
    asm volatile("cp.async.cg.shared.global [%0], [%1], 16;" :: "r"(s), "l"(g));
}
__device__ __forceinline__ void mma16816(float* d,
    uint32_t a0, uint32_t a1, uint32_t a2, uint32_t a3, uint32_t b0, uint32_t b1) {
    asm volatile(
        "mma.sync.aligned.m16n8k16.row.col.f32.bf16.bf16.f32 "
        "{%0,%1,%2,%3}, {%4,%5,%6,%7}, {%8,%9}, {%0,%1,%2,%3};"
        : "+f"(d[0]), "+f"(d[1]), "+f"(d[2]), "+f"(d[3])
        : "r"(a0), "r"(a1), "r"(a2), "r"(a3), "r"(b0), "r"(b1));
}
__device__ __forceinline__ void ldm_x4(uint32_t* r, uint32_t addr) {
    asm volatile("ldmatrix.sync.aligned.m8n8.x4.shared.b16 {%0,%1,%2,%3}, [%4];"
        : "=r"(r[0]), "=r"(r[1]), "=r"(r[2]), "=r"(r[3]) : "r"(addr));
}
__device__ __forceinline__ uint32_t pack_bf16x2(float lo, float hi) {
    uint32_t r;
    asm("cvt.rn.bf16x2.f32 %0, %1, %2;" : "=r"(r) : "f"(hi), "f"(lo));
    return r;
}
__device__ __forceinline__ void split2(float p0, float p1, uint32_t& h, uint32_t& l) {
    h = pack_bf16x2(p0, p1);
    __nv_bfloat162 hv = *reinterpret_cast<__nv_bfloat162*>(&h);
    l = pack_bf16x2(p0 - __bfloat162float(hv.x), p1 - __bfloat162float(hv.y));
}
__device__ __forceinline__ void bar_pair(int id) {
    asm volatile("bar.sync %0, 64;" :: "r"(id) : "memory");
}
__device__ __forceinline__ float ex2(float x) {
    float y;
    asm("ex2.approx.ftz.f32 %0, %1;" : "=f"(y) : "f"(x));
    return y;
}

// ---------------- Kernel 0: fp32 -> bf16 hi/lo split ----------------
__global__ __launch_bounds__(256) void split_x(const float* __restrict__ src)
{
    int i = blockIdx.x * blockDim.x + threadIdx.x;
    float4 v = *(const float4*)(src + 4*i);
    __nv_bfloat16 h0 = __float2bfloat16_rn(v.x), h1 = __float2bfloat16_rn(v.y);
    __nv_bfloat16 h2 = __float2bfloat16_rn(v.z), h3 = __float2bfloat16_rn(v.w);
    __nv_bfloat16 l0 = __float2bfloat16_rn(v.x - __bfloat162float(h0));
    __nv_bfloat16 l1 = __float2bfloat16_rn(v.y - __bfloat162float(h1));
    __nv_bfloat16 l2 = __float2bfloat16_rn(v.z - __bfloat162float(h2));
    __nv_bfloat16 l3 = __float2bfloat16_rn(v.w - __bfloat162float(h3));
    ((__nv_bfloat162*)g_Xhi)[2*i]   = __nv_bfloat162(h0, h1);
    ((__nv_bfloat162*)g_Xhi)[2*i+1] = __nv_bfloat162(h2, h3);
    ((__nv_bfloat162*)g_Xlo)[2*i]   = __nv_bfloat162(l0, l1);
    ((__nv_bfloat162*)g_Xlo)[2*i+1] = __nv_bfloat162(l2, l3);
}
__global__ __launch_bounds__(256) void split_w3(const float* __restrict__ Wq,
                                                const float* __restrict__ Wk,
                                                const float* __restrict__ Wv)
{
    int mat = blockIdx.y;
    const float* __restrict__ src = (mat == 0) ? Wq : ((mat == 1) ? Wk : Wv);
    int i = blockIdx.x * blockDim.x + threadIdx.x;
    size_t base = (size_t)mat * HD * HD / 2;
    float4 v = *(const float4*)(src + 4*i);
    __nv_bfloat16 h0 = __float2bfloat16_rn(v.x), h1 = __float2bfloat16_rn(v.y);
    __nv_bfloat16 h2 = __float2bfloat16_rn(v.z), h3 = __float2bfloat16_rn(v.w);
    __nv_bfloat16 l0 = __float2bfloat16_rn(v.x - __bfloat162float(h0));
    __nv_bfloat16 l1 = __float2bfloat16_rn(v.y - __bfloat162float(h1));
    __nv_bfloat16 l2 = __float2bfloat16_rn(v.z - __bfloat162float(h2));
    __nv_bfloat16 l3 = __float2bfloat16_rn(v.w - __bfloat162float(h3));
    ((__nv_bfloat162*)g_Whi)[base + 2*i]   = __nv_bfloat162(h0, h1);
    ((__nv_bfloat162*)g_Whi)[base + 2*i+1] = __nv_bfloat162(h2, h3);
    ((__nv_bfloat162*)g_Wlo)[base + 2*i]   = __nv_bfloat162(l0, l1);
    ((__nv_bfloat162*)g_Wlo)[base + 2*i+1] = __nv_bfloat162(l2, l3);
}

// ---------------- Kernel 1: QKV GEMM via mma.sync + ldmatrix ----------------
#define KS 32
#define NST (HD/KS)
#define ARRB (128*80)
#define STAGEB (4*ARRB)

__global__ __launch_bounds__(256, 2) void qkv_mma()
{
    extern __shared__ char smem[];
    const int t = threadIdx.x, lane = t & 31, wid = t >> 5;
    const int wm = wid & 1, wn = wid >> 1;
    const int g = lane >> 2, qd = lane & 3;
    const int mat = blockIdx.z;
    const int m0 = blockIdx.y * 128, n0 = blockIdx.x * 128;
    const __nv_bfloat16* __restrict__ Bhp = g_Whi + (size_t)mat * HD * HD;
    const __nv_bfloat16* __restrict__ Blp = g_Wlo + (size_t)mat * HD * HD;
    uint32_t sb = smem_u32(smem);

    float acc[4][4][4] = {};

    const uint32_t arow_off = (uint32_t)((wm*64 + (lane & 15)) * 80 + (lane >> 4) * 16);
    const uint32_t brow_off = (uint32_t)((wn*32 + (lane & 7) + ((lane >> 4) << 3)) * 80
                                         + ((lane >> 3) & 1) * 16);

    auto stage = [&](int s, int bsel) {
        int kt = s * KS;
        uint32_t base = sb + bsel * STAGEB;
        #pragma unroll
        for (int i = 0; i < 2; i++) {
            int c = t + i * 256;
            int row = c >> 2, seg = c & 3;
            uint32_t so = row * 80 + seg * 16;
            size_t ga = (size_t)(m0 + row) * HD + kt + seg * 8;
            size_t gb = (size_t)(n0 + row) * HD + kt + seg * 8;
            cp16(base + so,          g_Xhi + ga);
            cp16(base + ARRB + so,   g_Xlo + ga);
            cp16(base + 2*ARRB + so, Bhp + gb);
            cp16(base + 3*ARRB + so, Blp + gb);
        }
        asm volatile("cp.async.commit_group;" ::: "memory");
    };

    stage(0, 0);
    int buf = 0;
    for (int s = 0; s < NST; s++) {
        if (s + 1 < NST) {
            stage(s + 1, buf ^ 1);
            asm volatile("cp.async.wait_group 1;" ::: "memory");
        } else {
            asm volatile("cp.async.wait_group 0;" ::: "memory");
        }
        __syncthreads();

        uint32_t sbase = sb + buf * STAGEB;
        #pragma unroll
        for (int ks = 0; ks < 2; ks++) {
            uint32_t bh4[2][4], bl4[2][4];
            #pragma unroll
            for (int ntp = 0; ntp < 2; ntp++) {
                uint32_t baddr = sbase + 2*ARRB + brow_off + ntp*(16*80) + ks*32;
                ldm_x4(bh4[ntp], baddr);
                ldm_x4(bl4[ntp], baddr + ARRB);
            }
            #pragma unroll
            for (int mt = 0; mt < 4; mt++) {
                uint32_t aaddr = sbase + arow_off + mt*(16*80) + ks*32;
                uint32_t ah[4], al[4];
                ldm_x4(ah, aaddr);
                ldm_x4(al, aaddr + ARRB);
                #pragma unroll
                for (int nt = 0; nt < 4; nt++) {
                    uint32_t b0 = bh4[nt>>1][(nt&1)*2], b1 = bh4[nt>>1][(nt&1)*2+1];
                    uint32_t c0 = bl4[nt>>1][(nt&1)*2], c1 = bl4[nt>>1][(nt&1)*2+1];
                    mma16816(acc[mt][nt], ah[0],ah[1],ah[2],ah[3], b0, b1);
                    mma16816(acc[mt][nt], al[0],al[1],al[2],al[3], b0, b1);
                    mma16816(acc[mt][nt], ah[0],ah[1],ah[2],ah[3], c0, c1);
                }
            }
        }
        __syncthreads();
        buf ^= 1;
    }

    if (mat == 2) {
        #pragma unroll
        for (int mt = 0; mt < 4; mt++) {
            int r = m0 + wm*64 + mt*16 + g;
            #pragma unroll
            for (int nt = 0; nt < 4; nt++) {
                int c = n0 + wn*32 + nt*8 + 2*qd;
                *(float2*)&g_V[(size_t)r*HD + c]     = make_float2(acc[mt][nt][0], acc[mt][nt][1]);
                *(float2*)&g_V[(size_t)(r+8)*HD + c] = make_float2(acc[mt][nt][2], acc[mt][nt][3]);
            }
        }
    } else {
        __nv_bfloat16* Hp = mat ? g_Khi : g_Qhi;
        __nv_bfloat16* Lp = mat ? g_Klo : g_Qlo;
        const float sc = mat ? 1.0f : SCALE_Q;  // fold softmax scale * log2(e) into Q
        #pragma unroll
        for (int mt = 0; mt < 4; mt++) {
            int r = m0 + wm*64 + mt*16 + g;
            #pragma unroll
            for (int nt = 0; nt < 4; nt++) {
                int c = n0 + wn*32 + nt*8 + 2*qd;
                #pragma unroll
                for (int half = 0; half < 2; half++) {
                    float v0 = acc[mt][nt][2*half]*sc, v1 = acc[mt][nt][2*half+1]*sc;
                    __nv_bfloat16 h0 = __float2bfloat16_rn(v0);
                    __nv_bfloat16 h1 = __float2bfloat16_rn(v1);
                    __nv_bfloat16 l0 = __float2bfloat16_rn(v0 - __bfloat162float(h0));
                    __nv_bfloat16 l1 = __float2bfloat16_rn(v1 - __bfloat162float(h1));
                    size_t off = (size_t)(r + 8*half)*HD + c;
                    *(__nv_bfloat162*)&Hp[off] = __nv_bfloat162(h0, h1);
                    *(__nv_bfloat162*)&Lp[off] = __nv_bfloat162(l0, l1);
                }
            }
        }
    }
}

// ---------------- Kernel 2: db4 DWT; cA -> out, cD -> transposed bf16 hi/lo ----------------
#define DW_SV 0
#define DW_CDH 4224
#define DW_CDL 25024
#define DWT_SMEM 45824

__global__ __launch_bounds__(256) void dwt_kernel(float* __restrict__ outA)
{
    extern __shared__ char dsm[];
    float* sv = (float*)(dsm + DW_SV);
    const int t = threadIdx.x, warp = t >> 5, lane = t & 31;
    const int bh = blockIdx.y, sblk = blockIdx.x;
    const int b = bh >> 3, h = bh & 7;

    for (int i = t; i < 845; i += 256) {
        ((uint32_t*)(dsm + DW_CDH + 67*260))[i] = 0;
        ((uint32_t*)(dsm + DW_CDL + 67*260))[i] = 0;
    }

    for (int iter = 0; iter < 16; iter++) {
        int sl = iter*8 + warp;
        int s  = sblk*128 + sl;
        int rid = bh*SS + s;
        float4 v4 = *(const float4*)&g_V[(size_t)(b*SS + s)*HD + h*DK + lane*4];
        *(float4*)&sv[warp*132 + lane*4] = v4;
        __syncwarp();
        #pragma unroll
        for (int jj = 0; jj < 3; jj++) {
            int j = lane + jj*32;
            if (j < WA) {
                float alo = 0.f, ahi = 0.f;
                #pragma unroll
                for (int tt = 0; tt < 8; tt++) {
                    int i2 = 2*j + tt;
                    int vi = (i2 <= 5) ? (5 - i2) : ((i2 <= 133) ? (i2 - 6) : (261 - i2));
                    float e = sv[warp*132 + vi];
                    alo += e * REV_LO[tt];
                    ahi += e * REV_HI[tt];
                }
                outA[(size_t)rid*WA + j] = alo;
                __nv_bfloat16 hv = __float2bfloat16_rn(ahi);
                __nv_bfloat16 lv = __float2bfloat16_rn(ahi - __bfloat162float(hv));
                *(__nv_bfloat16*)(dsm + DW_CDH + j*260 + sl*2) = hv;
                *(__nv_bfloat16*)(dsm + DW_CDL + j*260 + sl*2) = lv;
            }
        }
        __syncwarp();
    }
    __syncthreads();

    const size_t gbase = ((size_t)bh*80*SS + (size_t)sblk*128) >> 1;
    for (int i = t; i < 80*64; i += 256) {
        int w = i >> 6, c = i & 63;
        uint32_t vh = *(uint32_t*)(dsm + DW_CDH + w*260 + c*4);
        uint32_t vl = *(uint32_t*)(dsm + DW_CDL + w*260 + c*4);
        ((uint32_t*)g_cDh)[gbase + (size_t)w*(SS/2) + c] = vh;
        ((uint32_t*)g_cDl)[gbase + (size_t)w*(SS/2) + c] = vl;
    }
}

// ---------------- Kernel 3: register-resident flash attention (split cp.async groups) ----------------
// smem: QH 0, QL 17408, KH 34816, KL 52224 (64 x 272B rows);
//       CDH 69632, CDL 81152 (80 x 144B rows: [w][key]);
//       stats @92672: sm_mx[2][64], sm_sum[2][64].  Obuf overlays KH at epilogue.
#define QH_OFF 0
#define QL_OFF 17408
#define KH_OFF 34816
#define KL_OFF 52224
#define CDH_OFF 69632
#define CDL_OFF 81152
#define STAT_OFF 92672
#define ATTN_SMEM (STAT_OFF + 1024)
#define OBUF_OFF KH_OFF

__global__ __launch_bounds__(256, 2) void attn_kernel(float* __restrict__ out1)
{
    extern __shared__ char smem[];
    uint32_t sb = smem_u32(smem);
    float* sm_mx  = (float*)(smem + STAT_OFF);
    float* sm_sum = sm_mx + 128;

    const int t = threadIdx.x;
    const int lane = t & 31, wid = t >> 5;
    const int g = lane >> 2, qd = lane & 3;
    const int qg = wid >> 1, kh = wid & 1;     // warp = (query-group, key-half)
    const int bar_id = 1 + qg;                 // named barrier per warp pair
    const int bh = blockIdx.y;
    const int b  = bh >> 3;
    const int h  = bh & 7;
    const int q0 = blockIdx.x * 64;
    const int r0 = qg*16 + g, r1 = r0 + 8;

    // load Q tiles (hi/lo)
    for (int i = t; i < 64*16; i += 256) {
        int row = i >> 4, seg = i & 15;
        size_t go = (size_t)(b*SS + q0 + row)*HD + h*DK + seg*8;
        *(uint4*)(smem + QH_OFF + row*272 + seg*16) = *(const uint4*)(g_Qhi + go);
        *(uint4*)(smem + QL_OFF + row*272 + seg*16) = *(const uint4*)(g_Qlo + go);
    }

    float O[10][4] = {};
    float m0 = -1e30f, m1 = -1e30f, l0 = 0.f, l1 = 0.f;

    const uint32_t qbase = sb + QH_OFF + (uint32_t)((qg*16 + (lane & 15))*272 + (lane >> 4)*16);
    const uint32_t kbase = sb + KH_OFF
        + (uint32_t)((kh*32 + (lane & 7) + ((lane >> 4) << 3))*272 + ((lane >> 3) & 1)*16);
    const uint32_t cbase = sb + CDH_OFF
        + (uint32_t)(((lane & 7) + ((lane >> 4) << 3))*144 + ((lane >> 3) & 1)*16 + kh*64);
    __syncthreads();

    for (int k0c = 0; k0c < SS; k0c += 64) {
        // group 1: K chunk (needed for Phase A)
        for (int i = t; i < 64*16; i += 256) {
            int row = i >> 4, seg = i & 15;
            size_t go = (size_t)(b*SS + k0c + row)*HD + h*DK + seg*8;
            cp16(sb + KH_OFF + row*272 + seg*16, g_Khi + go);
            cp16(sb + KL_OFF + row*272 + seg*16, g_Klo + go);
        }
        asm volatile("cp.async.commit_group;" ::: "memory");
        // group 2: cD chunk (needed only in Phase C — stays in flight during A/B)
        for (int i = t; i < 80*8; i += 256) {
            int w = i >> 3, c = i & 7;
            size_t go = (size_t)(bh*80 + w)*SS + k0c + c*8;
            cp16(sb + CDH_OFF + w*144 + c*16, g_cDh + go);
            cp16(sb + CDL_OFF + w*144 + c*16, g_cDl + go);
        }
        asm volatile("cp.async.commit_group;" ::: "memory");

        asm volatile("cp.async.wait_group 1;" ::: "memory");   // K ready; cD in flight
        __syncthreads();

        // -------- Phase A: S (16q x 32k) in registers (log2-domain scores) --------
        float acc[4][4] = {};
        #pragma unroll
        for (int kb = 0; kb < 8; kb++) {
            uint32_t ah[4], al[4], b0h[4], b1h[4], b0l[4], b1l[4];
            ldm_x4(ah, qbase + kb*32);
            ldm_x4(al, qbase + kb*32 + (QL_OFF - QH_OFF));
            ldm_x4(b0h, kbase + kb*32);
            ldm_x4(b1h, kbase + kb*32 + 16*272);
            ldm_x4(b0l, kbase + kb*32 + (KL_OFF - KH_OFF));
            ldm_x4(b1l, kbase + kb*32 + 16*272 + (KL_OFF - KH_OFF));
            #pragma unroll
            for (int nt = 0; nt < 4; nt++) {
                uint32_t h0 = (nt < 2) ? b0h[(nt&1)*2]   : b1h[(nt&1)*2];
                uint32_t h1 = (nt < 2) ? b0h[(nt&1)*2+1] : b1h[(nt&1)*2+1];
                uint32_t c0 = (nt < 2) ? b0l[(nt&1)*2]   : b1l[(nt&1)*2];
                uint32_t c1 = (nt < 2) ? b0l[(nt&1)*2+1] : b1l[(nt&1)*2+1];
                mma16816(acc[nt], ah[0],ah[1],ah[2],ah[3], h0, h1);
                mma16816(acc[nt], al[0],al[1],al[2],al[3], h0, h1);
                mma16816(acc[nt], ah[0],ah[1],ah[2],ah[3], c0, c1);
            }
        }

        // -------- Phase B: softmax in registers (2^x domain) --------
        float mx0 = -1e30f, mx1 = -1e30f;
        #pragma unroll
        for (int nt = 0; nt < 4; nt++) {
            mx0 = fmaxf(mx0, fmaxf(acc[nt][0], acc[nt][1]));
            mx1 = fmaxf(mx1, fmaxf(acc[nt][2], acc[nt][3]));
        }
        mx0 = fmaxf(mx0, __shfl_xor_sync(0xffffffffu, mx0, 1));
        mx0 = fmaxf(mx0, __shfl_xor_sync(0xffffffffu, mx0, 2));
        mx1 = fmaxf(mx1, __shfl_xor_sync(0xffffffffu, mx1, 1));
        mx1 = fmaxf(mx1, __shfl_xor_sync(0xffffffffu, mx1, 2));
        if (qd == 0) { sm_mx[kh*64 + r0] = mx0; sm_mx[kh*64 + r1] = mx1; }
        bar_pair(bar_id);
        float mnew0 = fmaxf(m0, fmaxf(sm_mx[r0], sm_mx[64 + r0]));
        float mnew1 = fmaxf(m1, fmaxf(sm_mx[r1], sm_mx[64 + r1]));
        float fac0 = ex2(m0 - mnew0), fac1 = ex2(m1 - mnew1);
        float sum0 = 0.f, sum1 = 0.f;
        #pragma unroll
        for (int nt = 0; nt < 4; nt++) {
            acc[nt][0] = ex2(acc[nt][0] - mnew0);
            acc[nt][1] = ex2(acc[nt][1] - mnew0);
            acc[nt][2] = ex2(acc[nt][2] - mnew1);
            acc[nt][3] = ex2(acc[nt][3] - mnew1);
            sum0 += acc[nt][0] + acc[nt][1];
            sum1 += acc[nt][2] + acc[nt][3];
        }
        sum0 += __shfl_xor_sync(0xffffffffu, sum0, 1);
        sum0 += __shfl_xor_sync(0xffffffffu, sum0, 2);
        sum1 += __shfl_xor_sync(0xffffffffu, sum1, 1);
        sum1 += __shfl_xor_sync(0xffffffffu, sum1, 2);
        if (qd == 0) { sm_sum[kh*64 + r0] = sum0; sm_sum[kh*64 + r1] = sum1; }

        // convert P to bf16 hi/lo A-fragments while the pair barrier settles
        uint32_t pah[2][4], pal[2][4];
        #pragma unroll
        for (int kbi = 0; kbi < 2; kbi++) {
            int na = 2*kbi, nb = na + 1;
            split2(acc[na][0], acc[na][1], pah[kbi][0], pal[kbi][0]);
            split2(acc[na][2], acc[na][3], pah[kbi][1], pal[kbi][1]);
            split2(acc[nb][0], acc[nb][1], pah[kbi][2], pal[kbi][2]);
            split2(acc[nb][2], acc[nb][3], pah[kbi][3], pal[kbi][3]);
        }
        bar_pair(bar_id);
        l0 = l0*fac0 + sm_sum[r0] + sm_sum[64 + r0];
        l1 = l1*fac1 + sm_sum[r1] + sm_sum[64 + r1];
        m0 = mnew0; m1 = mnew1;

        // -------- Phase C: O = O*fac + P @ cD^T --------
        #pragma unroll
        for (int nt = 0; nt < 10; nt++) {
            O[nt][0] *= fac0; O[nt][1] *= fac0;
            O[nt][2] *= fac1; O[nt][3] *= fac1;
        }
        asm volatile("cp.async.wait_group 0;" ::: "memory");   // cD ready
        __syncthreads();
        #pragma unroll
        for (int kbi = 0; kbi < 2; kbi++) {
            #pragma unroll
            for (int ntp = 0; ntp < 5; ntp++) {
                uint32_t cb[4], cl[4];
                uint32_t ca = cbase + ntp*(16*144) + kbi*32;
                ldm_x4(cb, ca);
                ldm_x4(cl, ca + (CDL_OFF - CDH_OFF));
                mma16816(O[2*ntp],   pah[kbi][0],pah[kbi][1],pah[kbi][2],pah[kbi][3], cb[0], cb[1]);
                mma16816(O[2*ntp],   pal[kbi][0],pal[kbi][1],pal[kbi][2],pal[kbi][3], cb[0], cb[1]);
                mma16816(O[2*ntp],   pah[kbi][0],pah[kbi][1],pah[kbi][2],pah[kbi][3], cl[0], cl[1]);
                mma16816(O[2*ntp+1], pah[kbi][0],pah[kbi][1],pah[kbi][2],pah[kbi][3], cb[2], cb[3]);
                mma16816(O[2*ntp+1], pal[kbi][0],pal[kbi][1],pal[kbi][2],pal[kbi][3], cb[2], cb[3]);
                mma16816(O[2*ntp+1], pah[kbi][0],pah[kbi][1],pah[kbi][2],pah[kbi][3], cl[2], cl[3]);
            }
        }
        __syncthreads();   // protect stage buffers for next chunk's cp.async
    }

    // -------- epilogue: merge kh halves, divide by l, store --------
    float* Obuf = (float*)(smem + OBUF_OFF);   // [64][81] f32, overlays dead K tiles
    if (kh == 1) {
        #pragma unroll
        for (int nt = 0; nt < 10; nt++) {
            int w = nt*8 + 2*qd;
            Obuf[r0*81 + w]     = O[nt][0];
            Obuf[r0*81 + w + 1] = O[nt][1];
            Obuf[r1*81 + w]     = O[nt][2];
            Obuf[r1*81 + w + 1] = O[nt][3];
        }
    }
    __syncthreads();
    if (kh == 0) {
        float li0 = 1.f / l0, li1 = 1.f / l1;
        int qa = q0 + r0, qb2 = q0 + r1;
        #pragma unroll
        for (int nt = 0; nt < 10; nt++) {
            int w = nt*8 + 2*qd;
            if (w < WA) {
                out1[(size_t)(b*SS + qa)*OW + h*WA + w]  = (O[nt][0] + Obuf[r0*81 + w])*li0;
                out1[(size_t)(b*SS + qb2)*OW + h*WA + w] = (O[nt][2] + Obuf[r1*81 + w])*li1;
            }
            if (w + 1 < WA) {
                out1[(size_t)(b*SS + qa)*OW + h*WA + w + 1]  = (O[nt][1] + Obuf[r0*81 + w + 1])*li0;
                out1[(size_t)(b*SS + qb2)*OW + h*WA + w + 1] = (O[nt][3] + Obuf[r1*81 + w + 1])*li1;
            }
        }
    }
}

// ---------------- launch ----------------
extern "C" void kernel_launch(void* const* d_in, const int* in_sizes, int n_in,
                              void* d_out, int out_size)
{
    const float* x  = (const float*)d_in[0];
    const float* Wq = (const float*)d_in[1];
    const float* Wk = (const float*)d_in[2];
    const float* Wv = (const float*)d_in[3];
    float* out = (float*)d_out;

    (void)in_sizes; (void)n_in; (void)out_size;

    split_x<<<(BB*SS*HD/4 + 255)/256, 256>>>(x);
    split_w3<<<dim3(HD*HD/4/256, 3), 256>>>(Wq, Wk, Wv);

    cudaFuncSetAttribute(qkv_mma, cudaFuncAttributeMaxDynamicSharedMemorySize, 2*STAGEB);
    qkv_mma<<<dim3(HD/128, (BB*SS)/128, 3), 256, 2*STAGEB>>>();

    cudaFuncSetAttribute(dwt_kernel, cudaFuncAttributeMaxDynamicSharedMemorySize, DWT_SMEM);
    dwt_kernel<<<dim3(SS/128, BH), 256, DWT_SMEM>>>(out + OUT1_ELEMS);

    cudaFuncSetAttribute(attn_kernel, cudaFuncAttributeMaxDynamicSharedMemorySize, ATTN_SMEM);
    attn_kernel<<<dim3(SS/64, BH), 256, ATTN_SMEM>>>(out);
}

// round 15
// speedup vs baseline: 1.1819x; 1.0827x over previous
#include <cuda_runtime.h>
#include <cuda_bf16.h>
#include <cuda_fp16.h>
#include <math.h>
#include <stdint.h>

#define BB 4
#define SS 2048
#define HD 1024
#define NH 8
#define DK 128
#define WA 67
#define BH (BB*NH)
#define NROWS (BH*SS)
#define OUT1_ELEMS (BB*SS*NH*WA)
#define OW (NH*WA)
#define SCALE 0.08838834764831845f
// softmax scale with log2(e) folded in (scores computed directly in log2 domain)
#define SCALE_Q (0.08838834764831845f * 1.44269504088896340736f)

// ---------------- scratch (device globals; no allocation allowed) ----------------
__device__ float g_V[BB*SS*HD];
__device__ __half g_cD16[BH*80*SS];           // transposed fp16: [bh][w(80, zero-padded)][s]
__device__ __nv_bfloat16 g_Xhi[BB*SS*HD];
__device__ __nv_bfloat16 g_Xlo[BB*SS*HD];
__device__ __nv_bfloat16 g_Whi[3*HD*HD];
__device__ __nv_bfloat16 g_Wlo[3*HD*HD];
__device__ __nv_bfloat16 g_Qhi[BB*SS*HD];     // pre-scaled by SCALE*log2(e)
__device__ __nv_bfloat16 g_Qlo[BB*SS*HD];
__device__ __nv_bfloat16 g_Khi[BB*SS*HD];
__device__ __nv_bfloat16 g_Klo[BB*SS*HD];

// db4 filters, pre-reversed:  g[t] = DEC[7-t]
__constant__ float REV_LO[8] = {
    0.23037781330885523f,  0.7148465705525415f,   0.6308807679295904f,
   -0.02798376941698385f, -0.18703481171888114f,  0.030841381835986965f,
    0.032883011666982945f,-0.010597401784997278f };
__constant__ float REV_HI[8] = {
   -0.010597401784997278f,-0.032883011666982945f, 0.030841381835986965f,
    0.18703481171888114f, -0.02798376941698385f, -0.6308807679295904f,
    0.7148465705525415f,  -0.23037781330885523f };

// ---------------- helpers ----------------
__device__ __forceinline__ uint32_t smem_u32(const void* p) {
    uint32_t a;
    asm("{ .reg .u64 t; cvta.to.shared.u64 t, %1; cvt.u32.u64 %0, t; }" : "=r"(a) : "l"(p));
    return a;
}
__device__ __forceinline__ void cp16(uint32_t s, const void* g) {
    asm volatile("cp.async.cg.shared.global [%0], [%1], 16;" :: "r"(s), "l"(g));
}
__device__ __forceinline__ void mma16816(float* d,
    uint32_t a0, uint32_t a1, uint32_t a2, uint32_t a3, uint32_t b0, uint32_t b1) {
    asm volatile(
        "mma.sync.aligned.m16n8k16.row.col.f32.bf16.bf16.f32 "
        "{%0,%1,%2,%3}, {%4,%5,%6,%7}, {%8,%9}, {%0,%1,%2,%3};"
        : "+f"(d[0]), "+f"(d[1]), "+f"(d[2]), "+f"(d[3])
        : "r"(a0), "r"(a1), "r"(a2), "r"(a3), "r"(b0), "r"(b1));
}
__device__ __forceinline__ void mma16816h(float* d,
    uint32_t a0, uint32_t a1, uint32_t a2, uint32_t a3, uint32_t b0, uint32_t b1) {
    asm volatile(
        "mma.sync.aligned.m16n8k16.row.col.f32.f16.f16.f32 "
        "{%0,%1,%2,%3}, {%4,%5,%6,%7}, {%8,%9}, {%0,%1,%2,%3};"
        : "+f"(d[0]), "+f"(d[1]), "+f"(d[2]), "+f"(d[3])
        : "r"(a0), "r"(a1), "r"(a2), "r"(a3), "r"(b0), "r"(b1));
}
__device__ __forceinline__ void ldm_x4(uint32_t* r, uint32_t addr) {
    asm volatile("ldmatrix.sync.aligned.m8n8.x4.shared.b16 {%0,%1,%2,%3}, [%4];"
        : "=r"(r[0]), "=r"(r[1]), "=r"(r[2]), "=r"(r[3]) : "r"(addr));
}
__device__ __forceinline__ uint32_t pack_bf16x2(float lo, float hi) {
    uint32_t r;
    asm("cvt.rn.bf16x2.f32 %0, %1, %2;" : "=r"(r) : "f"(hi), "f"(lo));
    return r;
}
__device__ __forceinline__ uint32_t pack_f16x2(float lo, float hi) {
    uint32_t r;
    asm("cvt.rn.f16x2.f32 %0, %1, %2;" : "=r"(r) : "f"(hi), "f"(lo));
    return r;
}
__device__ __forceinline__ void bar_pair(int id) {
    asm volatile("bar.sync %0, 64;" :: "r"(id) : "memory");
}
__device__ __forceinline__ float ex2(float x) {
    float y;
    asm("ex2.approx.ftz.f32 %0, %1;" : "=f"(y) : "f"(x));
    return y;
}

// ---------------- Kernel 0: fp32 -> bf16 hi/lo split ----------------
__global__ __launch_bounds__(256) void split_x(const float* __restrict__ src)
{
    int i = blockIdx.x * blockDim.x + threadIdx.x;
    float4 v = *(const float4*)(src + 4*i);
    __nv_bfloat16 h0 = __float2bfloat16_rn(v.x), h1 = __float2bfloat16_rn(v.y);
    __nv_bfloat16 h2 = __float2bfloat16_rn(v.z), h3 = __float2bfloat16_rn(v.w);
    __nv_bfloat16 l0 = __float2bfloat16_rn(v.x - __bfloat162float(h0));
    __nv_bfloat16 l1 = __float2bfloat16_rn(v.y - __bfloat162float(h1));
    __nv_bfloat16 l2 = __float2bfloat16_rn(v.z - __bfloat162float(h2));
    __nv_bfloat16 l3 = __float2bfloat16_rn(v.w - __bfloat162float(h3));
    ((__nv_bfloat162*)g_Xhi)[2*i]   = __nv_bfloat162(h0, h1);
    ((__nv_bfloat162*)g_Xhi)[2*i+1] = __nv_bfloat162(h2, h3);
    ((__nv_bfloat162*)g_Xlo)[2*i]   = __nv_bfloat162(l0, l1);
    ((__nv_bfloat162*)g_Xlo)[2*i+1] = __nv_bfloat162(l2, l3);
}
__global__ __launch_bounds__(256) void split_w3(const float* __restrict__ Wq,
                                                const float* __restrict__ Wk,
                                                const float* __restrict__ Wv)
{
    int mat = blockIdx.y;
    const float* __restrict__ src = (mat == 0) ? Wq : ((mat == 1) ? Wk : Wv);
    int i = blockIdx.x * blockDim.x + threadIdx.x;
    size_t base = (size_t)mat * HD * HD / 2;
    float4 v = *(const float4*)(src + 4*i);
    __nv_bfloat16 h0 = __float2bfloat16_rn(v.x), h1 = __float2bfloat16_rn(v.y);
    __nv_bfloat16 h2 = __float2bfloat16_rn(v.z), h3 = __float2bfloat16_rn(v.w);
    __nv_bfloat16 l0 = __float2bfloat16_rn(v.x - __bfloat162float(h0));
    __nv_bfloat16 l1 = __float2bfloat16_rn(v.y - __bfloat162float(h1));
    __nv_bfloat16 l2 = __float2bfloat16_rn(v.z - __bfloat162float(h2));
    __nv_bfloat16 l3 = __float2bfloat16_rn(v.w - __bfloat162float(h3));
    ((__nv_bfloat162*)g_Whi)[base + 2*i]   = __nv_bfloat162(h0, h1);
    ((__nv_bfloat162*)g_Whi)[base + 2*i+1] = __nv_bfloat162(h2, h3);
    ((__nv_bfloat162*)g_Wlo)[base + 2*i]   = __nv_bfloat162(l0, l1);
    ((__nv_bfloat162*)g_Wlo)[base + 2*i+1] = __nv_bfloat162(l2, l3);
}

// ---------------- Kernel 1: QKV GEMM via mma.sync + ldmatrix ----------------
#define KS 32
#define NST (HD/KS)
#define ARRB (128*80)
#define STAGEB (4*ARRB)

__global__ __launch_bounds__(256, 2) void qkv_mma()
{
    extern __shared__ char smem[];
    const int t = threadIdx.x, lane = t & 31, wid = t >> 5;
    const int wm = wid & 1, wn = wid >> 1;
    const int g = lane >> 2, qd = lane & 3;
    const int mat = blockIdx.z;
    const int m0 = blockIdx.y * 128, n0 = blockIdx.x * 128;
    const __nv_bfloat16* __restrict__ Bhp = g_Whi + (size_t)mat * HD * HD;
    const __nv_bfloat16* __restrict__ Blp = g_Wlo + (size_t)mat * HD * HD;
    uint32_t sb = smem_u32(smem);

    float acc[4][4][4] = {};

    const uint32_t arow_off = (uint32_t)((wm*64 + (lane & 15)) * 80 + (lane >> 4) * 16);
    const uint32_t brow_off = (uint32_t)((wn*32 + (lane & 7) + ((lane >> 4) << 3)) * 80
                                         + ((lane >> 3) & 1) * 16);

    auto stage = [&](int s, int bsel) {
        int kt = s * KS;
        uint32_t base = sb + bsel * STAGEB;
        #pragma unroll
        for (int i = 0; i < 2; i++) {
            int c = t + i * 256;
            int row = c >> 2, seg = c & 3;
            uint32_t so = row * 80 + seg * 16;
            size_t ga = (size_t)(m0 + row) * HD + kt + seg * 8;
            size_t gb = (size_t)(n0 + row) * HD + kt + seg * 8;
            cp16(base + so,          g_Xhi + ga);
            cp16(base + ARRB + so,   g_Xlo + ga);
            cp16(base + 2*ARRB + so, Bhp + gb);
            cp16(base + 3*ARRB + so, Blp + gb);
        }
        asm volatile("cp.async.commit_group;" ::: "memory");
    };

    stage(0, 0);
    int buf = 0;
    for (int s = 0; s < NST; s++) {
        if (s + 1 < NST) {
            stage(s + 1, buf ^ 1);
            asm volatile("cp.async.wait_group 1;" ::: "memory");
        } else {
            asm volatile("cp.async.wait_group 0;" ::: "memory");
        }
        __syncthreads();

        uint32_t sbase = sb + buf * STAGEB;
        #pragma unroll
        for (int ks = 0; ks < 2; ks++) {
            uint32_t bh4[2][4], bl4[2][4];
            #pragma unroll
            for (int ntp = 0; ntp < 2; ntp++) {
                uint32_t baddr = sbase + 2*ARRB + brow_off + ntp*(16*80) + ks*32;
                ldm_x4(bh4[ntp], baddr);
                ldm_x4(bl4[ntp], baddr + ARRB);
            }
            #pragma unroll
            for (int mt = 0; mt < 4; mt++) {
                uint32_t aaddr = sbase + arow_off + mt*(16*80) + ks*32;
                uint32_t ah[4], al[4];
                ldm_x4(ah, aaddr);
                ldm_x4(al, aaddr + ARRB);
                #pragma unroll
                for (int nt = 0; nt < 4; nt++) {
                    uint32_t b0 = bh4[nt>>1][(nt&1)*2], b1 = bh4[nt>>1][(nt&1)*2+1];
                    uint32_t c0 = bl4[nt>>1][(nt&1)*2], c1 = bl4[nt>>1][(nt&1)*2+1];
                    mma16816(acc[mt][nt], ah[0],ah[1],ah[2],ah[3], b0, b1);
                    mma16816(acc[mt][nt], al[0],al[1],al[2],al[3], b0, b1);
                    mma16816(acc[mt][nt], ah[0],ah[1],ah[2],ah[3], c0, c1);
                }
            }
        }
        __syncthreads();
        buf ^= 1;
    }

    if (mat == 2) {
        #pragma unroll
        for (int mt = 0; mt < 4; mt++) {
            int r = m0 + wm*64 + mt*16 + g;
            #pragma unroll
            for (int nt = 0; nt < 4; nt++) {
                int c = n0 + wn*32 + nt*8 + 2*qd;
                *(float2*)&g_V[(size_t)r*HD + c]     = make_float2(acc[mt][nt][0], acc[mt][nt][1]);
                *(float2*)&g_V[(size_t)(r+8)*HD + c] = make_float2(acc[mt][nt][2], acc[mt][nt][3]);
            }
        }
    } else {
        __nv_bfloat16* Hp = mat ? g_Khi : g_Qhi;
        __nv_bfloat16* Lp = mat ? g_Klo : g_Qlo;
        const float sc = mat ? 1.0f : SCALE_Q;  // fold softmax scale * log2(e) into Q
        #pragma unroll
        for (int mt = 0; mt < 4; mt++) {
            int r = m0 + wm*64 + mt*16 + g;
            #pragma unroll
            for (int nt = 0; nt < 4; nt++) {
                int c = n0 + wn*32 + nt*8 + 2*qd;
                #pragma unroll
                for (int half = 0; half < 2; half++) {
                    float v0 = acc[mt][nt][2*half]*sc, v1 = acc[mt][nt][2*half+1]*sc;
                    __nv_bfloat16 h0 = __float2bfloat16_rn(v0);
                    __nv_bfloat16 h1 = __float2bfloat16_rn(v1);
                    __nv_bfloat16 l0 = __float2bfloat16_rn(v0 - __bfloat162float(h0));
                    __nv_bfloat16 l1 = __float2bfloat16_rn(v1 - __bfloat162float(h1));
                    size_t off = (size_t)(r + 8*half)*HD + c;
                    *(__nv_bfloat162*)&Hp[off] = __nv_bfloat162(h0, h1);
                    *(__nv_bfloat162*)&Lp[off] = __nv_bfloat162(l0, l1);
                }
            }
        }
    }
}

// ---------------- Kernel 2: db4 DWT; cA -> out, cD -> transposed fp16 ----------------
#define DW_SV 0
#define DW_CDH 4224
#define DWT_SMEM (DW_CDH + 80*260)

__global__ __launch_bounds__(256) void dwt_kernel(float* __restrict__ outA)
{
    extern __shared__ char dsm[];
    float* sv = (float*)(dsm + DW_SV);
    const int t = threadIdx.x, warp = t >> 5, lane = t & 31;
    const int bh = blockIdx.y, sblk = blockIdx.x;
    const int b = bh >> 3, h = bh & 7;

    for (int i = t; i < 845; i += 256)
        ((uint32_t*)(dsm + DW_CDH + 67*260))[i] = 0;

    for (int iter = 0; iter < 16; iter++) {
        int sl = iter*8 + warp;
        int s  = sblk*128 + sl;
        int rid = bh*SS + s;
        float4 v4 = *(const float4*)&g_V[(size_t)(b*SS + s)*HD + h*DK + lane*4];
        *(float4*)&sv[warp*132 + lane*4] = v4;
        __syncwarp();
        #pragma unroll
        for (int jj = 0; jj < 3; jj++) {
            int j = lane + jj*32;
            if (j < WA) {
                float alo = 0.f, ahi = 0.f;
                #pragma unroll
                for (int tt = 0; tt < 8; tt++) {
                    int i2 = 2*j + tt;
                    int vi = (i2 <= 5) ? (5 - i2) : ((i2 <= 133) ? (i2 - 6) : (261 - i2));
                    float e = sv[warp*132 + vi];
                    alo += e * REV_LO[tt];
                    ahi += e * REV_HI[tt];
                }
                outA[(size_t)rid*WA + j] = alo;
                *(__half*)(dsm + DW_CDH + j*260 + sl*2) = __float2half_rn(ahi);
            }
        }
        __syncwarp();
    }
    __syncthreads();

    const size_t gbase = ((size_t)bh*80*SS + (size_t)sblk*128) >> 1;
    for (int i = t; i < 80*64; i += 256) {
        int w = i >> 6, c = i & 63;
        uint32_t vh = *(uint32_t*)(dsm + DW_CDH + w*260 + c*4);
        ((uint32_t*)g_cD16)[gbase + (size_t)w*(SS/2) + c] = vh;
    }
}

// ---------------- Kernel 3: register-resident flash attention (fp16 P@cD) ----------------
// smem: QH 0, QL 17408, KH 34816, KL 52224 (64 x 272B rows);
//       CDH 69632 (80 x 144B rows: [w][key], fp16);
//       stats @81152: sm_mx[2][64], sm_sum[2][64].  Obuf overlays KH at epilogue.
#define QH_OFF 0
#define QL_OFF 17408
#define KH_OFF 34816
#define KL_OFF 52224
#define CDH_OFF 69632
#define STAT_OFF 81152
#define ATTN_SMEM (STAT_OFF + 1024)
#define OBUF_OFF KH_OFF

__global__ __launch_bounds__(256, 2) void attn_kernel(float* __restrict__ out1)
{
    extern __shared__ char smem[];
    uint32_t sb = smem_u32(smem);
    float* sm_mx  = (float*)(smem + STAT_OFF);
    float* sm_sum = sm_mx + 128;

    const int t = threadIdx.x;
    const int lane = t & 31, wid = t >> 5;
    const int g = lane >> 2, qd = lane & 3;
    const int qg = wid >> 1, kh = wid & 1;     // warp = (query-group, key-half)
    const int bar_id = 1 + qg;                 // named barrier per warp pair
    const int bh = blockIdx.y;
    const int b  = bh >> 3;
    const int h  = bh & 7;
    const int q0 = blockIdx.x * 64;
    const int r0 = qg*16 + g, r1 = r0 + 8;

    // load Q tiles (hi/lo)
    for (int i = t; i < 64*16; i += 256) {
        int row = i >> 4, seg = i & 15;
        size_t go = (size_t)(b*SS + q0 + row)*HD + h*DK + seg*8;
        *(uint4*)(smem + QH_OFF + row*272 + seg*16) = *(const uint4*)(g_Qhi + go);
        *(uint4*)(smem + QL_OFF + row*272 + seg*16) = *(const uint4*)(g_Qlo + go);
    }

    float O[10][4] = {};
    float m0 = -1e30f, m1 = -1e30f, l0 = 0.f, l1 = 0.f;

    const uint32_t qbase = sb + QH_OFF + (uint32_t)((qg*16 + (lane & 15))*272 + (lane >> 4)*16);
    const uint32_t kbase = sb + KH_OFF
        + (uint32_t)((kh*32 + (lane & 7) + ((lane >> 4) << 3))*272 + ((lane >> 3) & 1)*16);
    const uint32_t cbase = sb + CDH_OFF
        + (uint32_t)(((lane & 7) + ((lane >> 4) << 3))*144 + ((lane >> 3) & 1)*16 + kh*64);
    __syncthreads();

    for (int k0c = 0; k0c < SS; k0c += 64) {
        // group 1: K chunk (needed for Phase A)
        for (int i = t; i < 64*16; i += 256) {
            int row = i >> 4, seg = i & 15;
            size_t go = (size_t)(b*SS + k0c + row)*HD + h*DK + seg*8;
            cp16(sb + KH_OFF + row*272 + seg*16, g_Khi + go);
            cp16(sb + KL_OFF + row*272 + seg*16, g_Klo + go);
        }
        asm volatile("cp.async.commit_group;" ::: "memory");
        // group 2: cD chunk (fp16; needed only in Phase C — stays in flight during A/B)
        for (int i = t; i < 80*8; i += 256) {
            int w = i >> 3, c = i & 7;
            size_t go = (size_t)(bh*80 + w)*SS + k0c + c*8;
            cp16(sb + CDH_OFF + w*144 + c*16, g_cD16 + go);
        }
        asm volatile("cp.async.commit_group;" ::: "memory");

        asm volatile("cp.async.wait_group 1;" ::: "memory");   // K ready; cD in flight
        __syncthreads();

        // -------- Phase A: S (16q x 32k) in registers (log2-domain scores) --------
        float acc[4][4] = {};
        #pragma unroll
        for (int kb = 0; kb < 8; kb++) {
            uint32_t ah[4], al[4], b0h[4], b1h[4], b0l[4], b1l[4];
            ldm_x4(ah, qbase + kb*32);
            ldm_x4(al, qbase + kb*32 + (QL_OFF - QH_OFF));
            ldm_x4(b0h, kbase + kb*32);
            ldm_x4(b1h, kbase + kb*32 + 16*272);
            ldm_x4(b0l, kbase + kb*32 + (KL_OFF - KH_OFF));
            ldm_x4(b1l, kbase + kb*32 + 16*272 + (KL_OFF - KH_OFF));
            #pragma unroll
            for (int nt = 0; nt < 4; nt++) {
                uint32_t h0 = (nt < 2) ? b0h[(nt&1)*2]   : b1h[(nt&1)*2];
                uint32_t h1 = (nt < 2) ? b0h[(nt&1)*2+1] : b1h[(nt&1)*2+1];
                uint32_t c0 = (nt < 2) ? b0l[(nt&1)*2]   : b1l[(nt&1)*2];
                uint32_t c1 = (nt < 2) ? b0l[(nt&1)*2+1] : b1l[(nt&1)*2+1];
                mma16816(acc[nt], ah[0],ah[1],ah[2],ah[3], h0, h1);
                mma16816(acc[nt], al[0],al[1],al[2],al[3], h0, h1);
                mma16816(acc[nt], ah[0],ah[1],ah[2],ah[3], c0, c1);
            }
        }

        // -------- Phase B: softmax in registers (2^x domain) --------
        float mx0 = -1e30f, mx1 = -1e30f;
        #pragma unroll
        for (int nt = 0; nt < 4; nt++) {
            mx0 = fmaxf(mx0, fmaxf(acc[nt][0], acc[nt][1]));
            mx1 = fmaxf(mx1, fmaxf(acc[nt][2], acc[nt][3]));
        }
        mx0 = fmaxf(mx0, __shfl_xor_sync(0xffffffffu, mx0, 1));
        mx0 = fmaxf(mx0, __shfl_xor_sync(0xffffffffu, mx0, 2));
        mx1 = fmaxf(mx1, __shfl_xor_sync(0xffffffffu, mx1, 1));
        mx1 = fmaxf(mx1, __shfl_xor_sync(0xffffffffu, mx1, 2));
        if (qd == 0) { sm_mx[kh*64 + r0] = mx0; sm_mx[kh*64 + r1] = mx1; }
        bar_pair(bar_id);
        float mnew0 = fmaxf(m0, fmaxf(sm_mx[r0], sm_mx[64 + r0]));
        float mnew1 = fmaxf(m1, fmaxf(sm_mx[r1], sm_mx[64 + r1]));
        float fac0 = ex2(m0 - mnew0), fac1 = ex2(m1 - mnew1);
        float sum0 = 0.f, sum1 = 0.f;
        #pragma unroll
        for (int nt = 0; nt < 4; nt++) {
            acc[nt][0] = ex2(acc[nt][0] - mnew0);
            acc[nt][1] = ex2(acc[nt][1] - mnew0);
            acc[nt][2] = ex2(acc[nt][2] - mnew1);
            acc[nt][3] = ex2(acc[nt][3] - mnew1);
            sum0 += acc[nt][0] + acc[nt][1];
            sum1 += acc[nt][2] + acc[nt][3];
        }
        sum0 += __shfl_xor_sync(0xffffffffu, sum0, 1);
        sum0 += __shfl_xor_sync(0xffffffffu, sum0, 2);
        sum1 += __shfl_xor_sync(0xffffffffu, sum1, 1);
        sum1 += __shfl_xor_sync(0xffffffffu, sum1, 2);
        if (qd == 0) { sm_sum[kh*64 + r0] = sum0; sm_sum[kh*64 + r1] = sum1; }

        // convert P to fp16 A-fragments while the pair barrier settles
        uint32_t pah[2][4];
        #pragma unroll
        for (int kbi = 0; kbi < 2; kbi++) {
            int na = 2*kbi, nb = na + 1;
            pah[kbi][0] = pack_f16x2(acc[na][0], acc[na][1]);
            pah[kbi][1] = pack_f16x2(acc[na][2], acc[na][3]);
            pah[kbi][2] = pack_f16x2(acc[nb][0], acc[nb][1]);
            pah[kbi][3] = pack_f16x2(acc[nb][2], acc[nb][3]);
        }
        bar_pair(bar_id);
        l0 = l0*fac0 + sm_sum[r0] + sm_sum[64 + r0];
        l1 = l1*fac1 + sm_sum[r1] + sm_sum[64 + r1];
        m0 = mnew0; m1 = mnew1;

        // -------- Phase C: O = O*fac + P @ cD^T (fp16 x fp16, f32 accum) --------
        #pragma unroll
        for (int nt = 0; nt < 10; nt++) {
            O[nt][0] *= fac0; O[nt][1] *= fac0;
            O[nt][2] *= fac1; O[nt][3] *= fac1;
        }
        asm volatile("cp.async.wait_group 0;" ::: "memory");   // cD ready
        __syncthreads();
        #pragma unroll
        for (int kbi = 0; kbi < 2; kbi++) {
            #pragma unroll
            for (int ntp = 0; ntp < 5; ntp++) {
                uint32_t cb[4];
                ldm_x4(cb, cbase + ntp*(16*144) + kbi*32);
                mma16816h(O[2*ntp],   pah[kbi][0],pah[kbi][1],pah[kbi][2],pah[kbi][3], cb[0], cb[1]);
                mma16816h(O[2*ntp+1], pah[kbi][0],pah[kbi][1],pah[kbi][2],pah[kbi][3], cb[2], cb[3]);
            }
        }
        __syncthreads();   // protect stage buffers for next chunk's cp.async
    }

    // -------- epilogue: merge kh halves, divide by l, store --------
    float* Obuf = (float*)(smem + OBUF_OFF);   // [64][81] f32, overlays dead K tiles
    if (kh == 1) {
        #pragma unroll
        for (int nt = 0; nt < 10; nt++) {
            int w = nt*8 + 2*qd;
            Obuf[r0*81 + w]     = O[nt][0];
            Obuf[r0*81 + w + 1] = O[nt][1];
            Obuf[r1*81 + w]     = O[nt][2];
            Obuf[r1*81 + w + 1] = O[nt][3];
        }
    }
    __syncthreads();
    if (kh == 0) {
        float li0 = 1.f / l0, li1 = 1.f / l1;
        int qa = q0 + r0, qb2 = q0 + r1;
        #pragma unroll
        for (int nt = 0; nt < 10; nt++) {
            int w = nt*8 + 2*qd;
            if (w < WA) {
                out1[(size_t)(b*SS + qa)*OW + h*WA + w]  = (O[nt][0] + Obuf[r0*81 + w])*li0;
                out1[(size_t)(b*SS + qb2)*OW + h*WA + w] = (O[nt][2] + Obuf[r1*81 + w])*li1;
            }
            if (w + 1 < WA) {
                out1[(size_t)(b*SS + qa)*OW + h*WA + w + 1]  = (O[nt][1] + Obuf[r0*81 + w + 1])*li0;
                out1[(size_t)(b*SS + qb2)*OW + h*WA + w + 1] = (O[nt][3] + Obuf[r1*81 + w + 1])*li1;
            }
        }
    }
}

// ---------------- launch ----------------
extern "C" void kernel_launch(void* const* d_in, const int* in_sizes, int n_in,
                              void* d_out, int out_size)
{
    const float* x  = (const float*)d_in[0];
    const float* Wq = (const float*)d_in[1];
    const float* Wk = (const float*)d_in[2];
    const float* Wv = (const float*)d_in[3];
    float* out = (float*)d_out;

    (void)in_sizes; (void)n_in; (void)out_size;

    split_x<<<(BB*SS*HD/4 + 255)/256, 256>>>(x);
    split_w3<<<dim3(HD*HD/4/256, 3), 256>>>(Wq, Wk, Wv);

    cudaFuncSetAttribute(qkv_mma, cudaFuncAttributeMaxDynamicSharedMemorySize, 2*STAGEB);
    qkv_mma<<<dim3(HD/128, (BB*SS)/128, 3), 256, 2*STAGEB>>>();

    cudaFuncSetAttribute(dwt_kernel, cudaFuncAttributeMaxDynamicSharedMemorySize, DWT_SMEM);
    dwt_kernel<<<dim3(SS/128, BH), 256, DWT_SMEM>>>(out + OUT1_ELEMS);

    cudaFuncSetAttribute(attn_kernel, cudaFuncAttributeMaxDynamicSharedMemorySize, ATTN_SMEM);
    attn_kernel<<<dim3(SS/64, BH), 256, ATTN_SMEM>>>(out);
}

// round 16
// speedup vs baseline: 1.3791x; 1.1668x over previous
#include <cuda_runtime.h>
#include <cuda_bf16.h>
#include <cuda_fp16.h>
#include <math.h>
#include <stdint.h>

#define BB 4
#define SS 2048
#define HD 1024
#define NH 8
#define DK 128
#define WA 67
#define BH (BB*NH)
#define NROWS (BH*SS)
#define OUT1_ELEMS (BB*SS*NH*WA)
#define OW (NH*WA)
#define SCALE 0.08838834764831845f
// softmax scale with log2(e) folded in (scores computed directly in log2 domain)
#define SCALE_Q (0.08838834764831845f * 1.44269504088896340736f)

// ---------------- scratch (device globals; no allocation allowed) ----------------
__device__ float g_V[BB*SS*HD];
__device__ __half g_cD16[BH*80*SS];           // transposed fp16: [bh][w(80, zero-padded)][s]
__device__ __nv_bfloat16 g_Xhi[BB*SS*HD];
__device__ __nv_bfloat16 g_Xlo[BB*SS*HD];
__device__ __nv_bfloat16 g_Whi[3*HD*HD];
__device__ __nv_bfloat16 g_Wlo[3*HD*HD];
__device__ __half g_Q16[BB*SS*HD];            // single fp16, pre-scaled by SCALE*log2(e)
__device__ __half g_K16[BB*SS*HD];            // single fp16

// db4 filters, pre-reversed:  g[t] = DEC[7-t]
__constant__ float REV_LO[8] = {
    0.23037781330885523f,  0.7148465705525415f,   0.6308807679295904f,
   -0.02798376941698385f, -0.18703481171888114f,  0.030841381835986965f,
    0.032883011666982945f,-0.010597401784997278f };
__constant__ float REV_HI[8] = {
   -0.010597401784997278f,-0.032883011666982945f, 0.030841381835986965f,
    0.18703481171888114f, -0.02798376941698385f, -0.6308807679295904f,
    0.7148465705525415f,  -0.23037781330885523f };

// ---------------- helpers ----------------
__device__ __forceinline__ uint32_t smem_u32(const void* p) {
    uint32_t a;
    asm("{ .reg .u64 t; cvta.to.shared.u64 t, %1; cvt.u32.u64 %0, t; }" : "=r"(a) : "l"(p));
    return a;
}
__device__ __forceinline__ void cp16(uint32_t s, const void* g) {
    asm volatile("cp.async.cg.shared.global [%0], [%1], 16;" :: "r"(s), "l"(g));
}
__device__ __forceinline__ void mma16816(float* d,
    uint32_t a0, uint32_t a1, uint32_t a2, uint32_t a3, uint32_t b0, uint32_t b1) {
    asm volatile(
        "mma.sync.aligned.m16n8k16.row.col.f32.bf16.bf16.f32 "
        "{%0,%1,%2,%3}, {%4,%5,%6,%7}, {%8,%9}, {%0,%1,%2,%3};"
        : "+f"(d[0]), "+f"(d[1]), "+f"(d[2]), "+f"(d[3])
        : "r"(a0), "r"(a1), "r"(a2), "r"(a3), "r"(b0), "r"(b1));
}
__device__ __forceinline__ void mma16816h(float* d,
    uint32_t a0, uint32_t a1, uint32_t a2, uint32_t a3, uint32_t b0, uint32_t b1) {
    asm volatile(
        "mma.sync.aligned.m16n8k16.row.col.f32.f16.f16.f32 "
        "{%0,%1,%2,%3}, {%4,%5,%6,%7}, {%8,%9}, {%0,%1,%2,%3};"
        : "+f"(d[0]), "+f"(d[1]), "+f"(d[2]), "+f"(d[3])
        : "r"(a0), "r"(a1), "r"(a2), "r"(a3), "r"(b0), "r"(b1));
}
__device__ __forceinline__ void ldm_x4(uint32_t* r, uint32_t addr) {
    asm volatile("ldmatrix.sync.aligned.m8n8.x4.shared.b16 {%0,%1,%2,%3}, [%4];"
        : "=r"(r[0]), "=r"(r[1]), "=r"(r[2]), "=r"(r[3]) : "r"(addr));
}
__device__ __forceinline__ uint32_t pack_f16x2(float lo, float hi) {
    uint32_t r;
    asm("cvt.rn.f16x2.f32 %0, %1, %2;" : "=r"(r) : "f"(hi), "f"(lo));
    return r;
}
__device__ __forceinline__ void bar_pair(int id) {
    asm volatile("bar.sync %0, 64;" :: "r"(id) : "memory");
}
__device__ __forceinline__ float ex2(float x) {
    float y;
    asm("ex2.approx.ftz.f32 %0, %1;" : "=f"(y) : "f"(x));
    return y;
}

// ---------------- Kernel 0: fp32 -> bf16 hi/lo split ----------------
__global__ __launch_bounds__(256) void split_x(const float* __restrict__ src)
{
    int i = blockIdx.x * blockDim.x + threadIdx.x;
    float4 v = *(const float4*)(src + 4*i);
    __nv_bfloat16 h0 = __float2bfloat16_rn(v.x), h1 = __float2bfloat16_rn(v.y);
    __nv_bfloat16 h2 = __float2bfloat16_rn(v.z), h3 = __float2bfloat16_rn(v.w);
    __nv_bfloat16 l0 = __float2bfloat16_rn(v.x - __bfloat162float(h0));
    __nv_bfloat16 l1 = __float2bfloat16_rn(v.y - __bfloat162float(h1));
    __nv_bfloat16 l2 = __float2bfloat16_rn(v.z - __bfloat162float(h2));
    __nv_bfloat16 l3 = __float2bfloat16_rn(v.w - __bfloat162float(h3));
    ((__nv_bfloat162*)g_Xhi)[2*i]   = __nv_bfloat162(h0, h1);
    ((__nv_bfloat162*)g_Xhi)[2*i+1] = __nv_bfloat162(h2, h3);
    ((__nv_bfloat162*)g_Xlo)[2*i]   = __nv_bfloat162(l0, l1);
    ((__nv_bfloat162*)g_Xlo)[2*i+1] = __nv_bfloat162(l2, l3);
}
__global__ __launch_bounds__(256) void split_w3(const float* __restrict__ Wq,
                                                const float* __restrict__ Wk,
                                                const float* __restrict__ Wv)
{
    int mat = blockIdx.y;
    const float* __restrict__ src = (mat == 0) ? Wq : ((mat == 1) ? Wk : Wv);
    int i = blockIdx.x * blockDim.x + threadIdx.x;
    size_t base = (size_t)mat * HD * HD / 2;
    float4 v = *(const float4*)(src + 4*i);
    __nv_bfloat16 h0 = __float2bfloat16_rn(v.x), h1 = __float2bfloat16_rn(v.y);
    __nv_bfloat16 h2 = __float2bfloat16_rn(v.z), h3 = __float2bfloat16_rn(v.w);
    __nv_bfloat16 l0 = __float2bfloat16_rn(v.x - __bfloat162float(h0));
    __nv_bfloat16 l1 = __float2bfloat16_rn(v.y - __bfloat162float(h1));
    __nv_bfloat16 l2 = __float2bfloat16_rn(v.z - __bfloat162float(h2));
    __nv_bfloat16 l3 = __float2bfloat16_rn(v.w - __bfloat162float(h3));
    ((__nv_bfloat162*)g_Whi)[base + 2*i]   = __nv_bfloat162(h0, h1);
    ((__nv_bfloat162*)g_Whi)[base + 2*i+1] = __nv_bfloat162(h2, h3);
    ((__nv_bfloat162*)g_Wlo)[base + 2*i]   = __nv_bfloat162(l0, l1);
    ((__nv_bfloat162*)g_Wlo)[base + 2*i+1] = __nv_bfloat162(l2, l3);
}

// ---------------- Kernel 1: QKV GEMM via mma.sync + ldmatrix ----------------
#define KS 32
#define NST (HD/KS)
#define ARRB (128*80)
#define STAGEB (4*ARRB)

__global__ __launch_bounds__(256, 2) void qkv_mma()
{
    extern __shared__ char smem[];
    const int t = threadIdx.x, lane = t & 31, wid = t >> 5;
    const int wm = wid & 1, wn = wid >> 1;
    const int g = lane >> 2, qd = lane & 3;
    const int mat = blockIdx.z;
    const int m0 = blockIdx.y * 128, n0 = blockIdx.x * 128;
    const __nv_bfloat16* __restrict__ Bhp = g_Whi + (size_t)mat * HD * HD;
    const __nv_bfloat16* __restrict__ Blp = g_Wlo + (size_t)mat * HD * HD;
    uint32_t sb = smem_u32(smem);

    float acc[4][4][4] = {};

    const uint32_t arow_off = (uint32_t)((wm*64 + (lane & 15)) * 80 + (lane >> 4) * 16);
    const uint32_t brow_off = (uint32_t)((wn*32 + (lane & 7) + ((lane >> 4) << 3)) * 80
                                         + ((lane >> 3) & 1) * 16);

    auto stage = [&](int s, int bsel) {
        int kt = s * KS;
        uint32_t base = sb + bsel * STAGEB;
        #pragma unroll
        for (int i = 0; i < 2; i++) {
            int c = t + i * 256;
            int row = c >> 2, seg = c & 3;
            uint32_t so = row * 80 + seg * 16;
            size_t ga = (size_t)(m0 + row) * HD + kt + seg * 8;
            size_t gb = (size_t)(n0 + row) * HD + kt + seg * 8;
            cp16(base + so,          g_Xhi + ga);
            cp16(base + ARRB + so,   g_Xlo + ga);
            cp16(base + 2*ARRB + so, Bhp + gb);
            cp16(base + 3*ARRB + so, Blp + gb);
        }
        asm volatile("cp.async.commit_group;" ::: "memory");
    };

    stage(0, 0);
    int buf = 0;
    for (int s = 0; s < NST; s++) {
        if (s + 1 < NST) {
            stage(s + 1, buf ^ 1);
            asm volatile("cp.async.wait_group 1;" ::: "memory");
        } else {
            asm volatile("cp.async.wait_group 0;" ::: "memory");
        }
        __syncthreads();

        uint32_t sbase = sb + buf * STAGEB;
        #pragma unroll
        for (int ks = 0; ks < 2; ks++) {
            uint32_t bh4[2][4], bl4[2][4];
            #pragma unroll
            for (int ntp = 0; ntp < 2; ntp++) {
                uint32_t baddr = sbase + 2*ARRB + brow_off + ntp*(16*80) + ks*32;
                ldm_x4(bh4[ntp], baddr);
                ldm_x4(bl4[ntp], baddr + ARRB);
            }
            #pragma unroll
            for (int mt = 0; mt < 4; mt++) {
                uint32_t aaddr = sbase + arow_off + mt*(16*80) + ks*32;
                uint32_t ah[4], al[4];
                ldm_x4(ah, aaddr);
                ldm_x4(al, aaddr + ARRB);
                #pragma unroll
                for (int nt = 0; nt < 4; nt++) {
                    uint32_t b0 = bh4[nt>>1][(nt&1)*2], b1 = bh4[nt>>1][(nt&1)*2+1];
                    uint32_t c0 = bl4[nt>>1][(nt&1)*2], c1 = bl4[nt>>1][(nt&1)*2+1];
                    mma16816(acc[mt][nt], ah[0],ah[1],ah[2],ah[3], b0, b1);
                    mma16816(acc[mt][nt], al[0],al[1],al[2],al[3], b0, b1);
                    mma16816(acc[mt][nt], ah[0],ah[1],ah[2],ah[3], c0, c1);
                }
            }
        }
        __syncthreads();
        buf ^= 1;
    }

    if (mat == 2) {
        #pragma unroll
        for (int mt = 0; mt < 4; mt++) {
            int r = m0 + wm*64 + mt*16 + g;
            #pragma unroll
            for (int nt = 0; nt < 4; nt++) {
                int c = n0 + wn*32 + nt*8 + 2*qd;
                *(float2*)&g_V[(size_t)r*HD + c]     = make_float2(acc[mt][nt][0], acc[mt][nt][1]);
                *(float2*)&g_V[(size_t)(r+8)*HD + c] = make_float2(acc[mt][nt][2], acc[mt][nt][3]);
            }
        }
    } else {
        __half* Hp = mat ? g_K16 : g_Q16;
        const float sc = mat ? 1.0f : SCALE_Q;  // fold softmax scale * log2(e) into Q
        #pragma unroll
        for (int mt = 0; mt < 4; mt++) {
            int r = m0 + wm*64 + mt*16 + g;
            #pragma unroll
            for (int nt = 0; nt < 4; nt++) {
                int c = n0 + wn*32 + nt*8 + 2*qd;
                #pragma unroll
                for (int half = 0; half < 2; half++) {
                    float v0 = acc[mt][nt][2*half]*sc, v1 = acc[mt][nt][2*half+1]*sc;
                    size_t off = (size_t)(r + 8*half)*HD + c;
                    *(uint32_t*)&Hp[off] = pack_f16x2(v0, v1);
                }
            }
        }
    }
}

// ---------------- Kernel 2: db4 DWT; cA -> out, cD -> transposed fp16 ----------------
#define DW_SV 0
#define DW_CDH 4224
#define DWT_SMEM (DW_CDH + 80*260)

__global__ __launch_bounds__(256) void dwt_kernel(float* __restrict__ outA)
{
    extern __shared__ char dsm[];
    float* sv = (float*)(dsm + DW_SV);
    const int t = threadIdx.x, warp = t >> 5, lane = t & 31;
    const int bh = blockIdx.y, sblk = blockIdx.x;
    const int b = bh >> 3, h = bh & 7;

    for (int i = t; i < 845; i += 256)
        ((uint32_t*)(dsm + DW_CDH + 67*260))[i] = 0;

    for (int iter = 0; iter < 16; iter++) {
        int sl = iter*8 + warp;
        int s  = sblk*128 + sl;
        int rid = bh*SS + s;
        float4 v4 = *(const float4*)&g_V[(size_t)(b*SS + s)*HD + h*DK + lane*4];
        *(float4*)&sv[warp*132 + lane*4] = v4;
        __syncwarp();
        #pragma unroll
        for (int jj = 0; jj < 3; jj++) {
            int j = lane + jj*32;
            if (j < WA) {
                float alo = 0.f, ahi = 0.f;
                #pragma unroll
                for (int tt = 0; tt < 8; tt++) {
                    int i2 = 2*j + tt;
                    int vi = (i2 <= 5) ? (5 - i2) : ((i2 <= 133) ? (i2 - 6) : (261 - i2));
                    float e = sv[warp*132 + vi];
                    alo += e * REV_LO[tt];
                    ahi += e * REV_HI[tt];
                }
                outA[(size_t)rid*WA + j] = alo;
                *(__half*)(dsm + DW_CDH + j*260 + sl*2) = __float2half_rn(ahi);
            }
        }
        __syncwarp();
    }
    __syncthreads();

    const size_t gbase = ((size_t)bh*80*SS + (size_t)sblk*128) >> 1;
    for (int i = t; i < 80*64; i += 256) {
        int w = i >> 6, c = i & 63;
        uint32_t vh = *(uint32_t*)(dsm + DW_CDH + w*260 + c*4);
        ((uint32_t*)g_cD16)[gbase + (size_t)w*(SS/2) + c] = vh;
    }
}

// ---------------- Kernel 3: register-resident flash attention (all-fp16 operands) ----------------
// smem: Q16 0 (64 x 272B), K16 17408 (64 x 272B), CD 34816 (80 x 144B fp16);
//       stats @46336: sm_mx[2][64], sm_sum[2][64].  Obuf overlays K16 at epilogue.
#define Q16_OFF 0
#define K16_OFF 17408
#define CD_OFF 34816
#define STAT_OFF 46336
#define ATTN_SMEM (STAT_OFF + 1024)
#define OBUF_OFF K16_OFF

__global__ __launch_bounds__(256, 2) void attn_kernel(float* __restrict__ out1)
{
    extern __shared__ char smem[];
    uint32_t sb = smem_u32(smem);
    float* sm_mx  = (float*)(smem + STAT_OFF);
    float* sm_sum = sm_mx + 128;

    const int t = threadIdx.x;
    const int lane = t & 31, wid = t >> 5;
    const int g = lane >> 2, qd = lane & 3;
    const int qg = wid >> 1, kh = wid & 1;     // warp = (query-group, key-half)
    const int bar_id = 1 + qg;                 // named barrier per warp pair
    const int bh = blockIdx.y;
    const int b  = bh >> 3;
    const int h  = bh & 7;
    const int q0 = blockIdx.x * 64;
    const int r0 = qg*16 + g, r1 = r0 + 8;

    // load Q tile (single fp16)
    for (int i = t; i < 64*16; i += 256) {
        int row = i >> 4, seg = i & 15;
        size_t go = (size_t)(b*SS + q0 + row)*HD + h*DK + seg*8;
        *(uint4*)(smem + Q16_OFF + row*272 + seg*16) = *(const uint4*)(g_Q16 + go);
    }

    float O[10][4] = {};
    float m0 = -1e30f, m1 = -1e30f, l0 = 0.f, l1 = 0.f;

    const uint32_t qbase = sb + Q16_OFF + (uint32_t)((qg*16 + (lane & 15))*272 + (lane >> 4)*16);
    const uint32_t kbase = sb + K16_OFF
        + (uint32_t)((kh*32 + (lane & 7) + ((lane >> 4) << 3))*272 + ((lane >> 3) & 1)*16);
    const uint32_t cbase = sb + CD_OFF
        + (uint32_t)(((lane & 7) + ((lane >> 4) << 3))*144 + ((lane >> 3) & 1)*16 + kh*64);
    __syncthreads();

    for (int k0c = 0; k0c < SS; k0c += 64) {
        // group 1: K chunk (needed for Phase A)
        for (int i = t; i < 64*16; i += 256) {
            int row = i >> 4, seg = i & 15;
            size_t go = (size_t)(b*SS + k0c + row)*HD + h*DK + seg*8;
            cp16(sb + K16_OFF + row*272 + seg*16, g_K16 + go);
        }
        asm volatile("cp.async.commit_group;" ::: "memory");
        // group 2: cD chunk (needed only in Phase C — stays in flight during A/B)
        for (int i = t; i < 80*8; i += 256) {
            int w = i >> 3, c = i & 7;
            size_t go = (size_t)(bh*80 + w)*SS + k0c + c*8;
            cp16(sb + CD_OFF + w*144 + c*16, g_cD16 + go);
        }
        asm volatile("cp.async.commit_group;" ::: "memory");

        asm volatile("cp.async.wait_group 1;" ::: "memory");   // K ready; cD in flight
        __syncthreads();

        // -------- Phase A: S (16q x 32k) in registers, single fp16 mma --------
        float acc[4][4] = {};
        #pragma unroll
        for (int kb = 0; kb < 8; kb++) {
            uint32_t ah[4], b0[4], b1[4];
            ldm_x4(ah, qbase + kb*32);
            ldm_x4(b0, kbase + kb*32);
            ldm_x4(b1, kbase + kb*32 + 16*272);
            #pragma unroll
            for (int nt = 0; nt < 4; nt++) {
                uint32_t h0 = (nt < 2) ? b0[(nt&1)*2]   : b1[(nt&1)*2];
                uint32_t h1 = (nt < 2) ? b0[(nt&1)*2+1] : b1[(nt&1)*2+1];
                mma16816h(acc[nt], ah[0],ah[1],ah[2],ah[3], h0, h1);
            }
        }

        // -------- Phase B: softmax in registers (2^x domain) --------
        float mx0 = -1e30f, mx1 = -1e30f;
        #pragma unroll
        for (int nt = 0; nt < 4; nt++) {
            mx0 = fmaxf(mx0, fmaxf(acc[nt][0], acc[nt][1]));
            mx1 = fmaxf(mx1, fmaxf(acc[nt][2], acc[nt][3]));
        }
        mx0 = fmaxf(mx0, __shfl_xor_sync(0xffffffffu, mx0, 1));
        mx0 = fmaxf(mx0, __shfl_xor_sync(0xffffffffu, mx0, 2));
        mx1 = fmaxf(mx1, __shfl_xor_sync(0xffffffffu, mx1, 1));
        mx1 = fmaxf(mx1, __shfl_xor_sync(0xffffffffu, mx1, 2));
        if (qd == 0) { sm_mx[kh*64 + r0] = mx0; sm_mx[kh*64 + r1] = mx1; }
        bar_pair(bar_id);
        float mnew0 = fmaxf(m0, fmaxf(sm_mx[r0], sm_mx[64 + r0]));
        float mnew1 = fmaxf(m1, fmaxf(sm_mx[r1], sm_mx[64 + r1]));
        float fac0 = ex2(m0 - mnew0), fac1 = ex2(m1 - mnew1);
        float sum0 = 0.f, sum1 = 0.f;
        #pragma unroll
        for (int nt = 0; nt < 4; nt++) {
            acc[nt][0] = ex2(acc[nt][0] - mnew0);
            acc[nt][1] = ex2(acc[nt][1] - mnew0);
            acc[nt][2] = ex2(acc[nt][2] - mnew1);
            acc[nt][3] = ex2(acc[nt][3] - mnew1);
            sum0 += acc[nt][0] + acc[nt][1];
            sum1 += acc[nt][2] + acc[nt][3];
        }
        sum0 += __shfl_xor_sync(0xffffffffu, sum0, 1);
        sum0 += __shfl_xor_sync(0xffffffffu, sum0, 2);
        sum1 += __shfl_xor_sync(0xffffffffu, sum1, 1);
        sum1 += __shfl_xor_sync(0xffffffffu, sum1, 2);
        if (qd == 0) { sm_sum[kh*64 + r0] = sum0; sm_sum[kh*64 + r1] = sum1; }

        // convert P to fp16 A-fragments while the pair barrier settles
        uint32_t pah[2][4];
        #pragma unroll
        for (int kbi = 0; kbi < 2; kbi++) {
            int na = 2*kbi, nb = na + 1;
            pah[kbi][0] = pack_f16x2(acc[na][0], acc[na][1]);
            pah[kbi][1] = pack_f16x2(acc[na][2], acc[na][3]);
            pah[kbi][2] = pack_f16x2(acc[nb][0], acc[nb][1]);
            pah[kbi][3] = pack_f16x2(acc[nb][2], acc[nb][3]);
        }
        bar_pair(bar_id);
        l0 = l0*fac0 + sm_sum[r0] + sm_sum[64 + r0];
        l1 = l1*fac1 + sm_sum[r1] + sm_sum[64 + r1];
        m0 = mnew0; m1 = mnew1;

        // -------- Phase C: O = O*fac + P @ cD^T (fp16 x fp16, f32 accum) --------
        #pragma unroll
        for (int nt = 0; nt < 10; nt++) {
            O[nt][0] *= fac0; O[nt][1] *= fac0;
            O[nt][2] *= fac1; O[nt][3] *= fac1;
        }
        asm volatile("cp.async.wait_group 0;" ::: "memory");   // cD ready
        __syncthreads();
        #pragma unroll
        for (int kbi = 0; kbi < 2; kbi++) {
            #pragma unroll
            for (int ntp = 0; ntp < 5; ntp++) {
                uint32_t cb[4];
                ldm_x4(cb, cbase + ntp*(16*144) + kbi*32);
                mma16816h(O[2*ntp],   pah[kbi][0],pah[kbi][1],pah[kbi][2],pah[kbi][3], cb[0], cb[1]);
                mma16816h(O[2*ntp+1], pah[kbi][0],pah[kbi][1],pah[kbi][2],pah[kbi][3], cb[2], cb[3]);
            }
        }
        __syncthreads();   // protect stage buffers for next chunk's cp.async
    }

    // -------- epilogue: merge kh halves, divide by l, store --------
    float* Obuf = (float*)(smem + OBUF_OFF);   // [64][81] f32, overlays dead K tile
    if (kh == 1) {
        #pragma unroll
        for (int nt = 0; nt < 10; nt++) {
            int w = nt*8 + 2*qd;
            Obuf[r0*81 + w]     = O[nt][0];
            Obuf[r0*81 + w + 1] = O[nt][1];
            Obuf[r1*81 + w]     = O[nt][2];
            Obuf[r1*81 + w + 1] = O[nt][3];
        }
    }
    __syncthreads();
    if (kh == 0) {
        float li0 = 1.f / l0, li1 = 1.f / l1;
        int qa = q0 + r0, qb2 = q0 + r1;
        #pragma unroll
        for (int nt = 0; nt < 10; nt++) {
            int w = nt*8 + 2*qd;
            if (w < WA) {
                out1[(size_t)(b*SS + qa)*OW + h*WA + w]  = (O[nt][0] + Obuf[r0*81 + w])*li0;
                out1[(size_t)(b*SS + qb2)*OW + h*WA + w] = (O[nt][2] + Obuf[r1*81 + w])*li1;
            }
            if (w + 1 < WA) {
                out1[(size_t)(b*SS + qa)*OW + h*WA + w + 1]  = (O[nt][1] + Obuf[r0*81 + w + 1])*li0;
                out1[(size_t)(b*SS + qb2)*OW + h*WA + w + 1] = (O[nt][3] + Obuf[r1*81 + w + 1])*li1;
            }
        }
    }
}

// ---------------- launch ----------------
extern "C" void kernel_launch(void* const* d_in, const int* in_sizes, int n_in,
                              void* d_out, int out_size)
{
    const float* x  = (const float*)d_in[0];
    const float* Wq = (const float*)d_in[1];
    const float* Wk = (const float*)d_in[2];
    const float* Wv = (const float*)d_in[3];
    float* out = (float*)d_out;

    (void)in_sizes; (void)n_in; (void)out_size;

    split_x<<<(BB*SS*HD/4 + 255)/256, 256>>>(x);
    split_w3<<<dim3(HD*HD/4/256, 3), 256>>>(Wq, Wk, Wv);

    cudaFuncSetAttribute(qkv_mma, cudaFuncAttributeMaxDynamicSharedMemorySize, 2*STAGEB);
    qkv_mma<<<dim3(HD/128, (BB*SS)/128, 3), 256, 2*STAGEB>>>();

    cudaFuncSetAttribute(dwt_kernel, cudaFuncAttributeMaxDynamicSharedMemorySize, DWT_SMEM);
    dwt_kernel<<<dim3(SS/128, BH), 256, DWT_SMEM>>>(out + OUT1_ELEMS);

    cudaFuncSetAttribute(attn_kernel, cudaFuncAttributeMaxDynamicSharedMemorySize, ATTN_SMEM);
    attn_kernel<<<dim3(SS/64, BH), 256, ATTN_SMEM>>>(out);
}